// round 1
// baseline (speedup 1.0000x reference)
#include <cuda_runtime.h>
#include <cuda_bf16.h>
#include <math.h>
#include <float.h>

#define N_TOK 2048
#define HID   2048
#define HQ    16
#define D     128
#define NC    64
#define KS    32
#define STRIDE 32
#define BSZ   32
#define TOPK  8
#define WIN   512
#define SCALE 0.08838834764831845f  /* 1/sqrt(128) */
#define NEGF  -1e30f

// ---------------- scratch (device globals; no allocation allowed) ----------
__device__ float g_q   [N_TOK*HQ*D];
__device__ float g_k   [N_TOK*D];
__device__ float g_v   [N_TOK*D];
__device__ float g_ck  [NC*D];
__device__ float g_cv  [NC*D];
__device__ float g_blks[N_TOK*NC];
__device__ int   g_topk[N_TOK*TOPK];
__device__ float g_cmp [N_TOK*HQ*D];
__device__ float g_sp  [N_TOK*HQ*D];
__device__ float g_sw  [N_TOK*HQ*D];
__device__ float g_gate[N_TOK*HQ*3];
__device__ float g_att [N_TOK*HID];

// ---------------- generic fp32 tiled GEMM: C[N,M] = A[N,K] @ B[K,M] --------
#define BM 64
#define BN 64
#define BK 16
__global__ void sgemm_kernel(const float* __restrict__ A,
                             const float* __restrict__ B,
                             float* __restrict__ C,
                             int Nrows, int K, int M)
{
    __shared__ float As[BK][BM];
    __shared__ float Bs[BK][BN + 4];
    int tid  = threadIdx.x;                 // 256 threads
    int row0 = blockIdx.y * BM;
    int col0 = blockIdx.x * BN;
    int ty = tid >> 4, tx = tid & 15;       // 16x16 thread grid, 4x4 micro
    float acc[4][4];
#pragma unroll
    for (int i = 0; i < 4; i++)
#pragma unroll
        for (int j = 0; j < 4; j++) acc[i][j] = 0.f;

    for (int k0 = 0; k0 < K; k0 += BK) {
#pragma unroll
        for (int e = tid; e < BM*BK; e += 256) {
            int r = e >> 4, c = e & 15;
            As[c][r] = A[(size_t)(row0 + r) * K + k0 + c];
        }
#pragma unroll
        for (int e = tid; e < BK*BN; e += 256) {
            int r = e >> 6, c = e & 63;
            int col = col0 + c;
            Bs[r][c] = (col < M) ? B[(size_t)(k0 + r) * M + col] : 0.f;
        }
        __syncthreads();
#pragma unroll
        for (int kk = 0; kk < BK; kk++) {
            float av[4], bv[4];
#pragma unroll
            for (int i = 0; i < 4; i++) av[i] = As[kk][ty*4 + i];
#pragma unroll
            for (int j = 0; j < 4; j++) bv[j] = Bs[kk][tx*4 + j];
#pragma unroll
            for (int i = 0; i < 4; i++)
#pragma unroll
                for (int j = 0; j < 4; j++) acc[i][j] += av[i] * bv[j];
        }
        __syncthreads();
    }
#pragma unroll
    for (int i = 0; i < 4; i++) {
        int row = row0 + ty*4 + i;
#pragma unroll
        for (int j = 0; j < 4; j++) {
            int col = col0 + tx*4 + j;
            if (col < M) C[(size_t)row * M + col] = acc[i][j];
        }
    }
}

// ---------------- compressed k/v (pre-RoPE) --------------------------------
__global__ void compress_kernel(const float* __restrict__ k,
                                const float* __restrict__ v,
                                const float* __restrict__ pe,
                                float* __restrict__ ck,
                                float* __restrict__ cv)
{
    int m = blockIdx.x;       // 0..63
    int d = threadIdx.x;      // 0..127
    float sk = 0.f, sv = 0.f;
#pragma unroll 8
    for (int i = 0; i < KS; i++) {
        sk += k[(m*KS + i)*D + d] + pe[i*D + d];
        sv += v[(m*KS + i)*D + d];
    }
    ck[m*D + d] = sk * (1.f/KS);
    cv[m*D + d] = sv * (1.f/KS);
}

// ---------------- RoPE (in place) ------------------------------------------
__global__ void rope_kernel(float* __restrict__ x, int heads, int pos_stride)
{
    int row = blockIdx.x;
    int d   = threadIdx.x;    // 0..63
    float inv = powf(10000.f, -(float)d / 64.f);
    float ang = (float)(row * pos_stride) * inv;
    float c = cosf(ang), s = sinf(ang);
    for (int h = 0; h < heads; h++) {
        float* p = x + ((size_t)row*heads + h) * D;
        float x1 = p[d], x2 = p[d + 64];
        p[d]      = x1 * c - x2 * s;
        p[d + 64] = x2 * c + x1 * s;
    }
}

// ---------------- compressed attention: one block per token -----------------
__global__ void cmp_attn_kernel(const float* __restrict__ q,
                                const float* __restrict__ ck,
                                const float* __restrict__ cv,
                                float* __restrict__ out,
                                float* __restrict__ blks)
{
    int n = blockIdx.x;
    __shared__ float qs[HQ*D];        // 8 KB
    __shared__ float pcs[HQ][NC];     // 4 KB
    int tid = threadIdx.x;            // 256

    for (int e = tid; e < HQ*D; e += 256) qs[e] = q[(size_t)n*HQ*D + e];
    __syncthreads();

    // scores -> pcs (pre-softmax)
    for (int e = tid; e < HQ*NC; e += 256) {
        int h = e >> 6, m = e & (NC-1);
        float s = 0.f;
        const float* qp = qs + h*D;
        const float* cp = ck + m*D;
#pragma unroll 8
        for (int d = 0; d < D; d++) s += qp[d] * cp[d];
        s *= SCALE;
        bool valid = (n >= m*STRIDE + KS - 1);
        pcs[h][m] = valid ? s : NEGF;
    }
    __syncthreads();

    // per-head softmax (16 serial rows, threads 0..15)
    if (tid < HQ) {
        int h = tid;
        float mx = -FLT_MAX;
        for (int m = 0; m < NC; m++) mx = fmaxf(mx, pcs[h][m]);
        float sum = 0.f;
        for (int m = 0; m < NC; m++) { float e = expf(pcs[h][m] - mx); pcs[h][m] = e; sum += e; }
        float invs = 1.f / sum;
        for (int m = 0; m < NC; m++) {
            bool valid = (n >= m*STRIDE + KS - 1);
            pcs[h][m] = valid ? pcs[h][m] * invs : 0.f;
        }
    }
    __syncthreads();

    // block scores (sum over heads, fixed order -> deterministic)
    for (int m = tid; m < NC; m += 256) {
        float s = 0.f;
        for (int h = 0; h < HQ; h++) s += pcs[h][m];
        blks[(size_t)n*NC + m] = s;
    }

    // out_cmp
    for (int e = tid; e < HQ*D; e += 256) {
        int h = e >> 7, d = e & (D-1);
        float a = 0.f;
#pragma unroll 4
        for (int m = 0; m < NC; m++) a += pcs[h][m] * cv[m*D + d];
        out[(size_t)n*HQ*D + e] = a;
    }
}

// ---------------- top-k selection ------------------------------------------
__global__ void topk_kernel(const float* __restrict__ blks, int* __restrict__ topk)
{
    int n = blockIdx.x * blockDim.x + threadIdx.x;
    if (n >= N_TOK) return;
    float sel[NC];
    int tb = n / BSZ;
    for (int m = 0; m < NC; m++) {
        float s = blks[(size_t)n*NC + m];
        if (m > tb) s = NEGF;                               // future
        if (m < 1 || (m <= tb && m > tb - 2)) s = 1e30f;    // forced (INIT=1, LOCAL=2)
        sel[m] = s;
    }
    for (int j = 0; j < TOPK; j++) {
        int bi = 0; float bv = sel[0];
        for (int m = 1; m < NC; m++) if (sel[m] > bv) { bv = sel[m]; bi = m; }  // ties -> lowest idx
        topk[n*TOPK + j] = bi;
        sel[bi] = -FLT_MAX;
    }
}

// ---------------- shared-memory reduce helpers -----------------------------
__device__ __forceinline__ float blk_reduce_max(float v, float* red, int tid) {
    red[tid] = v; __syncthreads();
    for (int s = 128; s > 0; s >>= 1) { if (tid < s) red[tid] = fmaxf(red[tid], red[tid+s]); __syncthreads(); }
    float r = red[0]; __syncthreads();
    return r;
}
__device__ __forceinline__ float blk_reduce_sum(float v, float* red, int tid) {
    red[tid] = v; __syncthreads();
    for (int s = 128; s > 0; s >>= 1) { if (tid < s) red[tid] += red[tid+s]; __syncthreads(); }
    float r = red[0]; __syncthreads();
    return r;
}

// ---------------- selected (top-k) attention: block per (token, head) -------
__global__ void sel_attn_kernel(const float* __restrict__ q,
                                const float* __restrict__ k,
                                const float* __restrict__ v,
                                const int* __restrict__ topk,
                                float* __restrict__ out)
{
    int n = blockIdx.x, h = blockIdx.y;
    __shared__ float qs[D];
    __shared__ float sc[TOPK*BSZ];    // 256
    __shared__ int   kp[TOPK*BSZ];
    __shared__ int   tks[TOPK];
    __shared__ float red[256];
    int tid = threadIdx.x;            // 256

    if (tid < D) qs[tid] = q[((size_t)n*HQ + h)*D + tid];
    if (tid < TOPK) tks[tid] = topk[n*TOPK + tid];
    __syncthreads();

    int pos = tks[tid >> 5] * BSZ + (tid & 31);
    kp[tid] = pos;
    float s;
    if (pos <= n) {
        s = 0.f;
        const float* kr = k + (size_t)pos * D;
#pragma unroll 8
        for (int d = 0; d < D; d++) s += qs[d] * kr[d];
        s *= SCALE;
    } else s = NEGF;
    __syncthreads();
    float mx  = blk_reduce_max(s, red, tid);
    float p   = expf(s - mx);
    float tot = blk_reduce_sum(p, red, tid);
    sc[tid] = p / tot;
    __syncthreads();

    if (tid < D) {
        float a = 0.f;
#pragma unroll 4
        for (int j = 0; j < TOPK*BSZ; j++) a += sc[j] * v[(size_t)kp[j]*D + tid];
        out[((size_t)n*HQ + h)*D + tid] = a;
    }
}

// ---------------- sliding-window attention: block per (token, head) ---------
__global__ void win_attn_kernel(const float* __restrict__ q,
                                const float* __restrict__ k,
                                const float* __restrict__ v,
                                float* __restrict__ out)
{
    int n = blockIdx.x, h = blockIdx.y;
    int lo  = n - WIN; if (lo < 0) lo = 0;
    int cnt = n - lo + 1;             // <= 513
    __shared__ float qs[D];
    __shared__ float sc[WIN + 8];
    __shared__ float red[256];
    int tid = threadIdx.x;            // 256

    if (tid < D) qs[tid] = q[((size_t)n*HQ + h)*D + tid];
    __syncthreads();

    float lmax = -FLT_MAX;
    for (int j = tid; j < cnt; j += 256) {
        float s = 0.f;
        const float* kr = k + (size_t)(lo + j) * D;
#pragma unroll 8
        for (int d = 0; d < D; d++) s += qs[d] * kr[d];
        s *= SCALE;
        sc[j] = s;
        lmax = fmaxf(lmax, s);
    }
    float mx = blk_reduce_max(lmax, red, tid);
    float lsum = 0.f;
    for (int j = tid; j < cnt; j += 256) {
        float p = expf(sc[j] - mx);
        sc[j] = p;
        lsum += p;
    }
    float tot = blk_reduce_sum(lsum, red, tid);
    float invs = 1.f / tot;
    __syncthreads();

    if (tid < D) {
        float a = 0.f;
#pragma unroll 4
        for (int j = 0; j < cnt; j++) a += sc[j] * v[(size_t)(lo + j)*D + tid];
        out[((size_t)n*HQ + h)*D + tid] = a * invs;
    }
}

// ---------------- gate combine ---------------------------------------------
__global__ void combine_kernel(const float* __restrict__ gbuf,
                               const float* __restrict__ cmp,
                               const float* __restrict__ sp,
                               const float* __restrict__ sw,
                               float* __restrict__ att)
{
    size_t idx = (size_t)blockIdx.x * 256 + threadIdx.x;  // over N*HQ*D
    int n = (int)(idx >> 11);
    int hd = (int)(idx & 2047);
    int h = hd >> 7;
    const float* g = gbuf + (size_t)n*HQ*3 + h*3;
    float g0 = 1.f / (1.f + expf(-g[0]));
    float g1 = 1.f / (1.f + expf(-g[1]));
    float g2 = 1.f / (1.f + expf(-g[2]));
    att[idx] = g0 * cmp[idx] + g1 * sp[idx] + g2 * sw[idx];
}

// ---------------- launcher --------------------------------------------------
extern "C" void kernel_launch(void* const* d_in, const int* in_sizes, int n_in,
                              void* d_out, int out_size)
{
    const float* x  = (const float*)d_in[0];
    // d_in[1] = cu_seqlens (single sequence; unused, matching reference)
    const float* Wq = (const float*)d_in[2];
    const float* Wk = (const float*)d_in[3];
    const float* Wv = (const float*)d_in[4];
    const float* Wo = (const float*)d_in[5];
    const float* Wg = (const float*)d_in[6];
    const float* pe = (const float*)d_in[7];
    float* out = (float*)d_out;

    float *q, *k, *v, *ck, *cv, *blks, *cmp, *sp, *sw, *gate, *att;
    int* tk;
    cudaGetSymbolAddress((void**)&q,    g_q);
    cudaGetSymbolAddress((void**)&k,    g_k);
    cudaGetSymbolAddress((void**)&v,    g_v);
    cudaGetSymbolAddress((void**)&ck,   g_ck);
    cudaGetSymbolAddress((void**)&cv,   g_cv);
    cudaGetSymbolAddress((void**)&blks, g_blks);
    cudaGetSymbolAddress((void**)&tk,   g_topk);
    cudaGetSymbolAddress((void**)&cmp,  g_cmp);
    cudaGetSymbolAddress((void**)&sp,   g_sp);
    cudaGetSymbolAddress((void**)&sw,   g_sw);
    cudaGetSymbolAddress((void**)&gate, g_gate);
    cudaGetSymbolAddress((void**)&att,  g_att);

    // projections
    sgemm_kernel<<<dim3(HQ*D/BN,  N_TOK/BM), 256>>>(x, Wq, q,    N_TOK, HID, HQ*D);
    sgemm_kernel<<<dim3(D/BN,     N_TOK/BM), 256>>>(x, Wk, k,    N_TOK, HID, D);
    sgemm_kernel<<<dim3(D/BN,     N_TOK/BM), 256>>>(x, Wv, v,    N_TOK, HID, D);
    sgemm_kernel<<<dim3(1,        N_TOK/BM), 256>>>(x, Wg, gate, N_TOK, HID, HQ*3);

    // compress (pre-RoPE k), then RoPE
    compress_kernel<<<NC, D>>>(k, v, pe, ck, cv);
    rope_kernel<<<N_TOK, 64>>>(q, HQ, 1);
    rope_kernel<<<N_TOK, 64>>>(k, 1, 1);
    rope_kernel<<<NC, 64>>>(ck, 1, STRIDE);

    // branches
    cmp_attn_kernel<<<N_TOK, 256>>>(q, ck, cv, cmp, blks);
    topk_kernel<<<N_TOK/256, 256>>>(blks, tk);
    sel_attn_kernel<<<dim3(N_TOK, HQ), 256>>>(q, k, v, tk, sp);
    win_attn_kernel<<<dim3(N_TOK, HQ), 256>>>(q, k, v, sw);

    // gate combine + output projection
    combine_kernel<<<(N_TOK*HQ*D)/256, 256>>>(gate, cmp, sp, sw, att);
    sgemm_kernel<<<dim3(HID/BN, N_TOK/BM), 256>>>(att, Wo, out, N_TOK, HID, HID);
}

// round 2
// speedup vs baseline: 3.9212x; 3.9212x over previous
#include <cuda_runtime.h>
#include <cuda_bf16.h>
#include <math.h>
#include <float.h>

#define N_TOK 2048
#define HID   2048
#define HQ    16
#define D     128
#define NC    64
#define KS    32
#define STRIDE 32
#define BSZ   32
#define TOPK  8
#define WIN   512
#define SCALE 0.08838834764831845f  /* 1/sqrt(128) */
#define NEGF  -1e30f

// ---------------- scratch (device globals) ---------------------------------
__device__ float g_q   [N_TOK*HQ*D];
__device__ float g_k   [N_TOK*D];
__device__ float g_v   [N_TOK*D];
__device__ float g_ck  [NC*D];
__device__ float g_cv  [NC*D];
__device__ float g_blks[N_TOK*NC];
__device__ int   g_topk[N_TOK*TOPK];
__device__ float g_cmp [N_TOK*HQ*D];
__device__ float g_sp  [N_TOK*HQ*D];
__device__ float g_sw  [N_TOK*HQ*D];
__device__ float g_gate[N_TOK*HQ*3];
__device__ float g_att [N_TOK*HID];

// ---------------- fp32 GEMM: C[rows,M] = A[rows,K] @ B[K,M], 128x128x8 ------
__global__ void __launch_bounds__(256, 2)
sgemm_kernel(const float* __restrict__ A, const float* __restrict__ B,
             float* __restrict__ C, int K, int M)
{
    __shared__ float As[8][132];
    __shared__ float Bs[8][128];
    int tid  = threadIdx.x;                 // 256
    int row0 = blockIdx.y * 128;
    int col0 = blockIdx.x * 128;
    int tx = tid & 15, ty = tid >> 4;
    int arow = tid >> 1, acol = (tid & 1) * 4;
    int brow = tid >> 5, bcol = (tid & 31) * 4;
    bool bval = (col0 + bcol + 4) <= M;

    float acc[8][8];
#pragma unroll
    for (int i = 0; i < 8; i++)
#pragma unroll
        for (int j = 0; j < 8; j++) acc[i][j] = 0.f;

    const float* Ap = A + (size_t)(row0 + arow) * K + acol;

    for (int k0 = 0; k0 < K; k0 += 8) {
        float4 a = *(const float4*)(Ap + k0);
        As[acol+0][arow] = a.x; As[acol+1][arow] = a.y;
        As[acol+2][arow] = a.z; As[acol+3][arow] = a.w;
        float4 b = bval ? *(const float4*)&B[(size_t)(k0 + brow) * M + col0 + bcol]
                        : make_float4(0.f,0.f,0.f,0.f);
        *(float4*)&Bs[brow][bcol] = b;
        __syncthreads();
#pragma unroll
        for (int kk = 0; kk < 8; kk++) {
            float4 a0 = *(const float4*)&As[kk][ty*8];
            float4 a1 = *(const float4*)&As[kk][ty*8+4];
            float4 b0 = *(const float4*)&Bs[kk][tx*8];
            float4 b1 = *(const float4*)&Bs[kk][tx*8+4];
            float av[8] = {a0.x,a0.y,a0.z,a0.w,a1.x,a1.y,a1.z,a1.w};
            float bv[8] = {b0.x,b0.y,b0.z,b0.w,b1.x,b1.y,b1.z,b1.w};
#pragma unroll
            for (int i = 0; i < 8; i++)
#pragma unroll
                for (int j = 0; j < 8; j++) acc[i][j] += av[i] * bv[j];
        }
        __syncthreads();
    }
#pragma unroll
    for (int i = 0; i < 8; i++) {
        int r = row0 + ty*8 + i;
#pragma unroll
        for (int j4 = 0; j4 < 8; j4 += 4) {
            int c = col0 + tx*8 + j4;
            if (c + 4 <= M) {
                float4 o = make_float4(acc[i][j4], acc[i][j4+1], acc[i][j4+2], acc[i][j4+3]);
                *(float4*)&C[(size_t)r * M + c] = o;
            } else {
                for (int u = 0; u < 4; u++)
                    if (c + u < M) C[(size_t)r * M + c + u] = acc[i][j4+u];
            }
        }
    }
}

// ---------------- compressed k/v (pre-RoPE) --------------------------------
__global__ void compress_kernel(const float* __restrict__ k,
                                const float* __restrict__ v,
                                const float* __restrict__ pe,
                                float* __restrict__ ck,
                                float* __restrict__ cv)
{
    int m = blockIdx.x;
    int d = threadIdx.x;
    float sk = 0.f, sv = 0.f;
#pragma unroll 8
    for (int i = 0; i < KS; i++) {
        sk += k[(m*KS + i)*D + d] + pe[i*D + d];
        sv += v[(m*KS + i)*D + d];
    }
    ck[m*D + d] = sk * (1.f/KS);
    cv[m*D + d] = sv * (1.f/KS);
}

// ---------------- RoPE (in place) ------------------------------------------
__global__ void rope_kernel(float* __restrict__ x, int heads, int pos_stride)
{
    int row = blockIdx.x;
    int d   = threadIdx.x;    // 0..63
    float inv = powf(10000.f, -(float)d / 64.f);
    float ang = (float)(row * pos_stride) * inv;
    float c = cosf(ang), s = sinf(ang);
    for (int h = 0; h < heads; h++) {
        float* p = x + ((size_t)row*heads + h) * D;
        float x1 = p[d], x2 = p[d + 64];
        p[d]      = x1 * c - x2 * s;
        p[d + 64] = x2 * c + x1 * s;
    }
}

// ---------------- compressed attention: one block per token -----------------
__global__ void cmp_attn_kernel(const float* __restrict__ q,
                                const float* __restrict__ ck,
                                const float* __restrict__ cv,
                                float* __restrict__ out,
                                float* __restrict__ blks)
{
    int n = blockIdx.x;
    __shared__ float qs[HQ*D];
    __shared__ float pcs[HQ][NC];
    int tid = threadIdx.x;            // 256

    for (int e = tid; e < HQ*D/4; e += 256)
        ((float4*)qs)[e] = ((const float4*)(q + (size_t)n*HQ*D))[e];
    __syncthreads();

    for (int e = tid; e < HQ*NC; e += 256) {
        int h = e >> 6, m = e & (NC-1);
        float s = 0.f;
        const float* qp = qs + h*D;
        const float* cp = ck + m*D;
#pragma unroll 8
        for (int d = 0; d < D; d++) s += qp[d] * cp[d];
        s *= SCALE;
        bool valid = (n >= m*STRIDE + KS - 1);
        pcs[h][m] = valid ? s : NEGF;
    }
    __syncthreads();

    if (tid < HQ) {
        int h = tid;
        float mx = -FLT_MAX;
        for (int m = 0; m < NC; m++) mx = fmaxf(mx, pcs[h][m]);
        float sum = 0.f;
        for (int m = 0; m < NC; m++) { float e = __expf(pcs[h][m] - mx); pcs[h][m] = e; sum += e; }
        float invs = 1.f / sum;
        for (int m = 0; m < NC; m++) {
            bool valid = (n >= m*STRIDE + KS - 1);
            pcs[h][m] = valid ? pcs[h][m] * invs : 0.f;
        }
    }
    __syncthreads();

    for (int m = tid; m < NC; m += 256) {
        float s = 0.f;
        for (int h = 0; h < HQ; h++) s += pcs[h][m];
        blks[(size_t)n*NC + m] = s;
    }

    for (int e = tid; e < HQ*D; e += 256) {
        int h = e >> 7, d = e & (D-1);
        float a = 0.f;
#pragma unroll 4
        for (int m = 0; m < NC; m++) a += pcs[h][m] * cv[m*D + d];
        out[(size_t)n*HQ*D + e] = a;
    }
}

// ---------------- top-k selection ------------------------------------------
__global__ void topk_kernel(const float* __restrict__ blks, int* __restrict__ topk)
{
    int n = blockIdx.x * blockDim.x + threadIdx.x;
    if (n >= N_TOK) return;
    float sel[NC];
    int tb = n / BSZ;
    for (int m = 0; m < NC; m++) {
        float s = blks[(size_t)n*NC + m];
        if (m > tb) s = NEGF;
        if (m < 1 || (m <= tb && m > tb - 2)) s = 1e30f;
        sel[m] = s;
    }
    for (int j = 0; j < TOPK; j++) {
        int bi = 0; float bv = sel[0];
        for (int m = 1; m < NC; m++) if (sel[m] > bv) { bv = sel[m]; bi = m; }
        topk[n*TOPK + j] = bi;
        sel[bi] = -FLT_MAX;
    }
}

// ============ flash-style attention over a tile stream, all heads ===========
// Common pattern for win/sel: one block per token, 256 threads.
// smem: qs[16*128], kv[64*132] (padded rows), sc[16*64], stats.

#define KVP 132   /* padded row stride (floats) for 64x128 tile */

__device__ __forceinline__ void attn_tile_scores(
    const float* qs, const float* kv, float* sc, int tid, int tl, int n_unused)
{
    int jj = tid & 63;
    int hb = (tid >> 6) * 4;                 // heads hb..hb+3
    float s0 = 0.f, s1 = 0.f, s2 = 0.f, s3 = 0.f;
    if (jj < tl) {
        const float4* kr = (const float4*)(kv + jj * KVP);
        const float4* q0 = (const float4*)(qs + (hb+0) * D);
        const float4* q1 = (const float4*)(qs + (hb+1) * D);
        const float4* q2 = (const float4*)(qs + (hb+2) * D);
        const float4* q3 = (const float4*)(qs + (hb+3) * D);
#pragma unroll
        for (int c = 0; c < 32; c++) {
            float4 kk = kr[c];
            float4 a;
            a = q0[c]; s0 += a.x*kk.x + a.y*kk.y + a.z*kk.z + a.w*kk.w;
            a = q1[c]; s1 += a.x*kk.x + a.y*kk.y + a.z*kk.z + a.w*kk.w;
            a = q2[c]; s2 += a.x*kk.x + a.y*kk.y + a.z*kk.z + a.w*kk.w;
            a = q3[c]; s3 += a.x*kk.x + a.y*kk.y + a.z*kk.z + a.w*kk.w;
        }
        sc[(hb+0)*64 + jj] = s0 * SCALE;
        sc[(hb+1)*64 + jj] = s1 * SCALE;
        sc[(hb+2)*64 + jj] = s2 * SCALE;
        sc[(hb+3)*64 + jj] = s3 * SCALE;
    } else {
        sc[(hb+0)*64 + jj] = NEGF;
        sc[(hb+1)*64 + jj] = NEGF;
        sc[(hb+2)*64 + jj] = NEGF;
        sc[(hb+3)*64 + jj] = NEGF;
    }
}

__device__ __forceinline__ void attn_softmax_update(
    float* sc, float* mS, float* lS, float* fS, int tid)
{
    int h = tid >> 4, t = tid & 15;
    float4 sv = *(float4*)&sc[h*64 + t*4];
    float pm = fmaxf(fmaxf(sv.x, sv.y), fmaxf(sv.z, sv.w));
#pragma unroll
    for (int o = 1; o < 16; o <<= 1) pm = fmaxf(pm, __shfl_xor_sync(0xffffffff, pm, o));
    float mOld = mS[h];
    float mNew = fmaxf(mOld, pm);
    float4 p;
    p.x = __expf(sv.x - mNew); p.y = __expf(sv.y - mNew);
    p.z = __expf(sv.z - mNew); p.w = __expf(sv.w - mNew);
    *(float4*)&sc[h*64 + t*4] = p;
    float ps = p.x + p.y + p.z + p.w;
#pragma unroll
    for (int o = 1; o < 16; o <<= 1) ps += __shfl_xor_sync(0xffffffff, ps, o);
    if (t == 0) {
        float f = __expf(mOld - mNew);
        fS[h] = f;
        lS[h] = lS[h] * f + ps;
        mS[h] = mNew;
    }
}

// ---------------- sliding-window attention (all heads per token) ------------
__global__ void __launch_bounds__(256, 2)
win_attn_kernel(const float* __restrict__ q, const float* __restrict__ k,
                const float* __restrict__ v, float* __restrict__ out)
{
    int n = blockIdx.x;
    int tid = threadIdx.x;
    __shared__ float qs[HQ*D];
    __shared__ float kv[64*KVP];
    __shared__ float sc[HQ*64];
    __shared__ float mS[HQ], lS[HQ], fS[HQ];

    int lo  = n - WIN; if (lo < 0) lo = 0;
    int cnt = n - lo + 1;

    for (int e = tid; e < HQ*D/4; e += 256)
        ((float4*)qs)[e] = ((const float4*)(q + (size_t)n*HQ*D))[e];
    if (tid < HQ) { mS[tid] = -FLT_MAX; lS[tid] = 0.f; }

    int d  = tid & 127;
    int hg = tid >> 7;                 // heads hg*8 .. hg*8+7
    float acc[8];
#pragma unroll
    for (int i = 0; i < 8; i++) acc[i] = 0.f;
    __syncthreads();

    for (int t0 = 0; t0 < cnt; t0 += 64) {
        int tl = cnt - t0; if (tl > 64) tl = 64;
        // K tile
        for (int e = tid; e < 64*32; e += 256) {
            int row = e >> 5, c = e & 31;
            if (row < tl)
                *(float4*)&kv[row*KVP + c*4] = ((const float4*)(k + (size_t)(lo + t0 + row)*D))[c];
        }
        __syncthreads();
        attn_tile_scores(qs, kv, sc, tid, tl, n);
        __syncthreads();
        attn_softmax_update(sc, mS, lS, fS, tid);
        __syncthreads();
        // V tile (overwrites kv)
        for (int e = tid; e < 64*32; e += 256) {
            int row = e >> 5, c = e & 31;
            if (row < tl)
                *(float4*)&kv[row*KVP + c*4] = ((const float4*)(v + (size_t)(lo + t0 + row)*D))[c];
        }
        __syncthreads();
        {
#pragma unroll
            for (int i = 0; i < 8; i++) acc[i] *= fS[hg*8 + i];
            for (int j = 0; j < tl; j++) {
                float vj = kv[j*KVP + d];
#pragma unroll
                for (int i = 0; i < 8; i++) acc[i] += sc[(hg*8 + i)*64 + j] * vj;
            }
        }
        __syncthreads();
    }
#pragma unroll
    for (int i = 0; i < 8; i++) {
        int h = hg*8 + i;
        out[((size_t)n*HQ + h)*D + d] = acc[i] / lS[h];
    }
}

// ---------------- selected (top-k) attention (all heads per token) ----------
__global__ void __launch_bounds__(256, 2)
sel_attn_kernel(const float* __restrict__ q, const float* __restrict__ k,
                const float* __restrict__ v, const int* __restrict__ topk,
                float* __restrict__ out)
{
    int n = blockIdx.x;
    int tid = threadIdx.x;
    __shared__ float qs[HQ*D];
    __shared__ float kv[64*KVP];
    __shared__ float sc[HQ*64];
    __shared__ int   posA[TOPK*BSZ];
    __shared__ float mS[HQ], lS[HQ], fS[HQ];

    for (int e = tid; e < HQ*D/4; e += 256)
        ((float4*)qs)[e] = ((const float4*)(q + (size_t)n*HQ*D))[e];
    if (tid < HQ) { mS[tid] = -FLT_MAX; lS[tid] = 0.f; }
    posA[tid] = topk[n*TOPK + (tid >> 5)] * BSZ + (tid & 31);

    int d  = tid & 127;
    int hg = tid >> 7;
    float acc[8];
#pragma unroll
    for (int i = 0; i < 8; i++) acc[i] = 0.f;
    __syncthreads();

    for (int t0 = 0; t0 < TOPK*BSZ; t0 += 64) {
        // gather K tile
        for (int e = tid; e < 64*32; e += 256) {
            int row = e >> 5, c = e & 31;
            *(float4*)&kv[row*KVP + c*4] = ((const float4*)(k + (size_t)posA[t0 + row]*D))[c];
        }
        __syncthreads();
        {   // scores with causal mask on gathered positions
            int jj = tid & 63;
            int hb = (tid >> 6) * 4;
            bool valid = posA[t0 + jj] <= n;
            float s0=0.f,s1=0.f,s2=0.f,s3=0.f;
            if (valid) {
                const float4* kr = (const float4*)(kv + jj*KVP);
                const float4* q0 = (const float4*)(qs + (hb+0)*D);
                const float4* q1 = (const float4*)(qs + (hb+1)*D);
                const float4* q2 = (const float4*)(qs + (hb+2)*D);
                const float4* q3 = (const float4*)(qs + (hb+3)*D);
#pragma unroll
                for (int c = 0; c < 32; c++) {
                    float4 kk = kr[c];
                    float4 a;
                    a = q0[c]; s0 += a.x*kk.x + a.y*kk.y + a.z*kk.z + a.w*kk.w;
                    a = q1[c]; s1 += a.x*kk.x + a.y*kk.y + a.z*kk.z + a.w*kk.w;
                    a = q2[c]; s2 += a.x*kk.x + a.y*kk.y + a.z*kk.z + a.w*kk.w;
                    a = q3[c]; s3 += a.x*kk.x + a.y*kk.y + a.z*kk.z + a.w*kk.w;
                }
                sc[(hb+0)*64+jj]=s0*SCALE; sc[(hb+1)*64+jj]=s1*SCALE;
                sc[(hb+2)*64+jj]=s2*SCALE; sc[(hb+3)*64+jj]=s3*SCALE;
            } else {
                sc[(hb+0)*64+jj]=NEGF; sc[(hb+1)*64+jj]=NEGF;
                sc[(hb+2)*64+jj]=NEGF; sc[(hb+3)*64+jj]=NEGF;
            }
        }
        __syncthreads();
        attn_softmax_update(sc, mS, lS, fS, tid);
        __syncthreads();
        // gather V tile
        for (int e = tid; e < 64*32; e += 256) {
            int row = e >> 5, c = e & 31;
            *(float4*)&kv[row*KVP + c*4] = ((const float4*)(v + (size_t)posA[t0 + row]*D))[c];
        }
        __syncthreads();
        {
#pragma unroll
            for (int i = 0; i < 8; i++) acc[i] *= fS[hg*8 + i];
            for (int j = 0; j < 64; j++) {
                float vj = kv[j*KVP + d];
#pragma unroll
                for (int i = 0; i < 8; i++) acc[i] += sc[(hg*8 + i)*64 + j] * vj;
            }
        }
        __syncthreads();
    }
#pragma unroll
    for (int i = 0; i < 8; i++) {
        int h = hg*8 + i;
        out[((size_t)n*HQ + h)*D + d] = acc[i] / lS[h];
    }
}

// ---------------- gate combine ---------------------------------------------
__global__ void combine_kernel(const float* __restrict__ gbuf,
                               const float* __restrict__ cmp,
                               const float* __restrict__ sp,
                               const float* __restrict__ sw,
                               float* __restrict__ att)
{
    size_t idx = (size_t)blockIdx.x * 256 + threadIdx.x;
    int n = (int)(idx >> 11);
    int hd = (int)(idx & 2047);
    int h = hd >> 7;
    const float* g = gbuf + (size_t)n*HQ*3 + h*3;
    float g0 = 1.f / (1.f + __expf(-g[0]));
    float g1 = 1.f / (1.f + __expf(-g[1]));
    float g2 = 1.f / (1.f + __expf(-g[2]));
    att[idx] = g0 * cmp[idx] + g1 * sp[idx] + g2 * sw[idx];
}

// ---------------- launcher --------------------------------------------------
extern "C" void kernel_launch(void* const* d_in, const int* in_sizes, int n_in,
                              void* d_out, int out_size)
{
    const float* x  = (const float*)d_in[0];
    const float* Wq = (const float*)d_in[2];
    const float* Wk = (const float*)d_in[3];
    const float* Wv = (const float*)d_in[4];
    const float* Wo = (const float*)d_in[5];
    const float* Wg = (const float*)d_in[6];
    const float* pe = (const float*)d_in[7];
    float* out = (float*)d_out;

    float *q, *k, *v, *ck, *cv, *blks, *cmp, *sp, *sw, *gate, *att;
    int* tk;
    cudaGetSymbolAddress((void**)&q,    g_q);
    cudaGetSymbolAddress((void**)&k,    g_k);
    cudaGetSymbolAddress((void**)&v,    g_v);
    cudaGetSymbolAddress((void**)&ck,   g_ck);
    cudaGetSymbolAddress((void**)&cv,   g_cv);
    cudaGetSymbolAddress((void**)&blks, g_blks);
    cudaGetSymbolAddress((void**)&tk,   g_topk);
    cudaGetSymbolAddress((void**)&cmp,  g_cmp);
    cudaGetSymbolAddress((void**)&sp,   g_sp);
    cudaGetSymbolAddress((void**)&sw,   g_sw);
    cudaGetSymbolAddress((void**)&gate, g_gate);
    cudaGetSymbolAddress((void**)&att,  g_att);

    // projections (C = A[2048,2048] @ B)
    sgemm_kernel<<<dim3(16, 16), 256>>>(x, Wq, q,    HID, HQ*D);
    sgemm_kernel<<<dim3(1,  16), 256>>>(x, Wk, k,    HID, D);
    sgemm_kernel<<<dim3(1,  16), 256>>>(x, Wv, v,    HID, D);
    sgemm_kernel<<<dim3(1,  16), 256>>>(x, Wg, gate, HID, HQ*3);

    // compress (pre-RoPE k), then RoPE
    compress_kernel<<<NC, D>>>(k, v, pe, ck, cv);
    rope_kernel<<<N_TOK, 64>>>(q, HQ, 1);
    rope_kernel<<<N_TOK, 64>>>(k, 1, 1);
    rope_kernel<<<NC, 64>>>(ck, 1, STRIDE);

    // branches
    cmp_attn_kernel<<<N_TOK, 256>>>(q, ck, cv, cmp, blks);
    topk_kernel<<<N_TOK/256, 256>>>(blks, tk);
    sel_attn_kernel<<<N_TOK, 256>>>(q, k, v, tk, sp);
    win_attn_kernel<<<N_TOK, 256>>>(q, k, v, sw);

    // gate combine + output projection
    combine_kernel<<<(N_TOK*HQ*D)/256, 256>>>(gate, cmp, sp, sw, att);
    sgemm_kernel<<<dim3(16, 16), 256>>>(att, Wo, out, HID, HID);
}

// round 4
// speedup vs baseline: 4.2163x; 1.0753x over previous
#include <cuda_runtime.h>
#include <cuda_bf16.h>
#include <math.h>
#include <float.h>
#include <stdint.h>

#define N_TOK 2048
#define HID   2048
#define HQ    16
#define D     128
#define NC    64
#define KS    32
#define STRIDE 32
#define BSZ   32
#define TOPK  8
#define WIN   512
#define SCALE 0.08838834764831845f  /* 1/sqrt(128) */
#define NEGF  -1e30f

// ---------------- scratch (device globals) ---------------------------------
__device__ float g_q   [N_TOK*HQ*D];
__device__ float g_k   [N_TOK*D];
__device__ float g_v   [N_TOK*D];
__device__ float g_ck  [NC*D];
__device__ float g_cv  [NC*D];
__device__ float g_blks[N_TOK*NC];
__device__ int   g_topk[N_TOK*TOPK];
__device__ float g_cmp [N_TOK*HQ*D];
__device__ float g_sp  [N_TOK*HQ*D];
__device__ float g_sw  [N_TOK*HQ*D];
__device__ float g_gate[N_TOK*HQ*3];
__device__ float g_att [N_TOK*HID];
__device__ float g_part[8 * N_TOK * 128];   // split-K partials (max M=128)

// ---------------- 3xTF32 tensor-core GEMM -----------------------------------
// C[2048, M] = A[2048, K] @ B[K, M]; tiles 128x64x16; 8 warps (4 row x 2 col),
// warp tile 32x32 via m16n8k8 tf32 mma with hi/lo split (fp32-equivalent).
__device__ __forceinline__ uint32_t f2tf32(float f) {
    uint32_t u;
    asm("cvt.rna.tf32.f32 %0, %1;" : "=r"(u) : "f"(f));
    return u;
}
__device__ __forceinline__ void split_tf32(float x, uint32_t& hi, uint32_t& lo) {
    hi = f2tf32(x);
    lo = f2tf32(x - __uint_as_float(hi));
}
__device__ __forceinline__ void mma_tf32(float* c, const uint32_t* a,
                                         uint32_t b0, uint32_t b1) {
    asm volatile(
        "mma.sync.aligned.m16n8k8.row.col.f32.tf32.tf32.f32 "
        "{%0,%1,%2,%3}, {%4,%5,%6,%7}, {%8,%9}, {%0,%1,%2,%3};"
        : "+f"(c[0]), "+f"(c[1]), "+f"(c[2]), "+f"(c[3])
        : "r"(a[0]), "r"(a[1]), "r"(a[2]), "r"(a[3]), "r"(b0), "r"(b1));
}

__global__ void __launch_bounds__(256, 2)
gemm_tf32x3_kernel(const float* __restrict__ A, const float* __restrict__ B,
                   float* __restrict__ C, float* __restrict__ Cpart,
                   int K, int M)
{
    __shared__ uint32_t AsH[16][132];
    __shared__ uint32_t AsL[16][132];
    __shared__ uint32_t BsH[16][68];
    __shared__ uint32_t BsL[16][68];

    int tid = threadIdx.x;
    int wid = tid >> 5, lane = tid & 31;
    int row0 = blockIdx.y * 128;
    int col0 = blockIdx.x * 64;
    int wr = (wid & 3) * 32;
    int wc = (wid >> 2) * 32;
    int g  = lane >> 2, tg = lane & 3;

    int S  = gridDim.z;
    int Kc = K / S;
    int kbeg = blockIdx.z * Kc;

    int arow = tid >> 1, acol = (tid & 1) * 8;
    int brow = tid >> 4, bcol = (tid & 15) * 4;
    bool bval = (col0 + bcol + 4) <= M;

    float acc[2][4][4];
#pragma unroll
    for (int mi = 0; mi < 2; mi++)
#pragma unroll
        for (int ni = 0; ni < 4; ni++)
#pragma unroll
            for (int r = 0; r < 4; r++) acc[mi][ni][r] = 0.f;

    const float* Ap = A + (size_t)(row0 + arow) * K + acol;

    for (int k0 = kbeg; k0 < kbeg + Kc; k0 += 16) {
        // A tile: 128 rows x 16 k, split hi/lo, stored [k][row]
        float4 a0 = *(const float4*)(Ap + k0);
        float4 a1 = *(const float4*)(Ap + k0 + 4);
        float av[8] = {a0.x,a0.y,a0.z,a0.w,a1.x,a1.y,a1.z,a1.w};
#pragma unroll
        for (int u = 0; u < 8; u++) {
            uint32_t hi, lo;
            split_tf32(av[u], hi, lo);
            AsH[acol+u][arow] = hi;
            AsL[acol+u][arow] = lo;
        }
        // B tile: 16 k x 64 cols
        {
            const float* Bp = B + (size_t)(k0 + brow) * M + col0 + bcol;
            float4 b = bval ? *(const float4*)Bp : make_float4(0,0,0,0);
            float bv[4] = {b.x,b.y,b.z,b.w};
#pragma unroll
            for (int u = 0; u < 4; u++) {
                uint32_t hi, lo;
                split_tf32(bv[u], hi, lo);
                BsH[brow][bcol+u] = hi;
                BsL[brow][bcol+u] = lo;
            }
        }
        __syncthreads();

#pragma unroll
        for (int ks = 0; ks < 16; ks += 8) {
            uint32_t afH[2][4], afL[2][4];
#pragma unroll
            for (int mi = 0; mi < 2; mi++) {
                int rb = wr + mi*16;
                afH[mi][0] = AsH[ks+tg  ][rb + g];
                afH[mi][1] = AsH[ks+tg  ][rb + g + 8];
                afH[mi][2] = AsH[ks+tg+4][rb + g];
                afH[mi][3] = AsH[ks+tg+4][rb + g + 8];
                afL[mi][0] = AsL[ks+tg  ][rb + g];
                afL[mi][1] = AsL[ks+tg  ][rb + g + 8];
                afL[mi][2] = AsL[ks+tg+4][rb + g];
                afL[mi][3] = AsL[ks+tg+4][rb + g + 8];
            }
#pragma unroll
            for (int ni = 0; ni < 4; ni++) {
                int col = wc + ni*8 + g;
                uint32_t bH0 = BsH[ks+tg  ][col];
                uint32_t bH1 = BsH[ks+tg+4][col];
                uint32_t bL0 = BsL[ks+tg  ][col];
                uint32_t bL1 = BsL[ks+tg+4][col];
#pragma unroll
                for (int mi = 0; mi < 2; mi++) {
                    mma_tf32(acc[mi][ni], afL[mi], bH0, bH1);
                    mma_tf32(acc[mi][ni], afH[mi], bL0, bL1);
                    mma_tf32(acc[mi][ni], afH[mi], bH0, bH1);
                }
            }
        }
        __syncthreads();
    }

    float* Cout = (S == 1) ? C : (Cpart + (size_t)blockIdx.z * N_TOK * M);
#pragma unroll
    for (int mi = 0; mi < 2; mi++) {
#pragma unroll
        for (int ni = 0; ni < 4; ni++) {
            int col = col0 + wc + ni*8 + tg*2;
            if (col < M) {
                int r0 = row0 + wr + mi*16 + g;
                float2 v0 = make_float2(acc[mi][ni][0], acc[mi][ni][1]);
                float2 v1 = make_float2(acc[mi][ni][2], acc[mi][ni][3]);
                *(float2*)&Cout[(size_t)r0 * M + col]       = v0;
                *(float2*)&Cout[(size_t)(r0 + 8) * M + col] = v1;
            }
        }
    }
}

// sum split-K partials
__global__ void splitk_reduce_kernel(const float* __restrict__ part,
                                     float* __restrict__ out, int len, int S)
{
    int i = blockIdx.x * 256 + threadIdx.x;
    if (i >= len) return;
    float s = 0.f;
    for (int z = 0; z < S; z++) s += part[(size_t)z * len + i];
    out[i] = s;
}

// ---------------- compressed k/v (pre-RoPE) --------------------------------
__global__ void compress_kernel(const float* __restrict__ k,
                                const float* __restrict__ v,
                                const float* __restrict__ pe,
                                float* __restrict__ ck,
                                float* __restrict__ cv)
{
    int m = blockIdx.x;
    int d = threadIdx.x;
    float sk = 0.f, sv = 0.f;
#pragma unroll 8
    for (int i = 0; i < KS; i++) {
        sk += k[(m*KS + i)*D + d] + pe[i*D + d];
        sv += v[(m*KS + i)*D + d];
    }
    ck[m*D + d] = sk * (1.f/KS);
    cv[m*D + d] = sv * (1.f/KS);
}

// ---------------- RoPE (in place) ------------------------------------------
__global__ void rope_kernel(float* __restrict__ x, int heads, int pos_stride)
{
    int row = blockIdx.x;
    int d   = threadIdx.x;    // 0..63
    float inv = powf(10000.f, -(float)d / 64.f);
    float ang = (float)(row * pos_stride) * inv;
    float c = cosf(ang), s = sinf(ang);
    for (int h = 0; h < heads; h++) {
        float* p = x + ((size_t)row*heads + h) * D;
        float x1 = p[d], x2 = p[d + 64];
        p[d]      = x1 * c - x2 * s;
        p[d + 64] = x2 * c + x1 * s;
    }
}

// ---------------- compressed attention: one block per token -----------------
__global__ void cmp_attn_kernel(const float* __restrict__ q,
                                const float* __restrict__ ck,
                                const float* __restrict__ cv,
                                float* __restrict__ out,
                                float* __restrict__ blks)
{
    int n = blockIdx.x;
    __shared__ float qs[HQ*D];
    __shared__ float pcs[HQ][NC];
    int tid = threadIdx.x;            // 256

    for (int e = tid; e < HQ*D/4; e += 256)
        ((float4*)qs)[e] = ((const float4*)(q + (size_t)n*HQ*D))[e];
    __syncthreads();

    for (int e = tid; e < HQ*NC; e += 256) {
        int h = e >> 6, m = e & (NC-1);
        float s = 0.f;
        const float* qp = qs + h*D;
        const float* cp = ck + m*D;
#pragma unroll 8
        for (int d = 0; d < D; d++) s += qp[d] * cp[d];
        s *= SCALE;
        bool valid = (n >= m*STRIDE + KS - 1);
        pcs[h][m] = valid ? s : NEGF;
    }
    __syncthreads();

    if (tid < HQ) {
        int h = tid;
        float mx = -FLT_MAX;
        for (int m = 0; m < NC; m++) mx = fmaxf(mx, pcs[h][m]);
        float sum = 0.f;
        for (int m = 0; m < NC; m++) { float e = __expf(pcs[h][m] - mx); pcs[h][m] = e; sum += e; }
        float invs = 1.f / sum;
        for (int m = 0; m < NC; m++) {
            bool valid = (n >= m*STRIDE + KS - 1);
            pcs[h][m] = valid ? pcs[h][m] * invs : 0.f;
        }
    }
    __syncthreads();

    for (int m = tid; m < NC; m += 256) {
        float s = 0.f;
        for (int h = 0; h < HQ; h++) s += pcs[h][m];
        blks[(size_t)n*NC + m] = s;
    }

    for (int e = tid; e < HQ*D; e += 256) {
        int h = e >> 7, d = e & (D-1);
        float a = 0.f;
#pragma unroll 4
        for (int m = 0; m < NC; m++) a += pcs[h][m] * cv[m*D + d];
        out[(size_t)n*HQ*D + e] = a;
    }
}

// ---------------- top-k selection ------------------------------------------
__global__ void topk_kernel(const float* __restrict__ blks, int* __restrict__ topk)
{
    int n = blockIdx.x * blockDim.x + threadIdx.x;
    if (n >= N_TOK) return;
    float sel[NC];
    int tb = n / BSZ;
    for (int m = 0; m < NC; m++) {
        float s = blks[(size_t)n*NC + m];
        if (m > tb) s = NEGF;
        if (m < 1 || (m <= tb && m > tb - 2)) s = 1e30f;
        sel[m] = s;
    }
    for (int j = 0; j < TOPK; j++) {
        int bi = 0; float bv = sel[0];
        for (int m = 1; m < NC; m++) if (sel[m] > bv) { bv = sel[m]; bi = m; }
        topk[n*TOPK + j] = bi;
        sel[bi] = -FLT_MAX;
    }
}

// ============ flash-style attention helpers =================================
#define KVP 132

__device__ __forceinline__ void attn_tile_scores(
    const float* qs, const float* kv, float* sc, int tid, int tl)
{
    int jj = tid & 63;
    int hb = (tid >> 6) * 4;
    float s0 = 0.f, s1 = 0.f, s2 = 0.f, s3 = 0.f;
    if (jj < tl) {
        const float4* kr = (const float4*)(kv + jj * KVP);
        const float4* q0 = (const float4*)(qs + (hb+0) * D);
        const float4* q1 = (const float4*)(qs + (hb+1) * D);
        const float4* q2 = (const float4*)(qs + (hb+2) * D);
        const float4* q3 = (const float4*)(qs + (hb+3) * D);
#pragma unroll
        for (int c = 0; c < 32; c++) {
            float4 kk = kr[c];
            float4 a;
            a = q0[c]; s0 += a.x*kk.x + a.y*kk.y + a.z*kk.z + a.w*kk.w;
            a = q1[c]; s1 += a.x*kk.x + a.y*kk.y + a.z*kk.z + a.w*kk.w;
            a = q2[c]; s2 += a.x*kk.x + a.y*kk.y + a.z*kk.z + a.w*kk.w;
            a = q3[c]; s3 += a.x*kk.x + a.y*kk.y + a.z*kk.z + a.w*kk.w;
        }
        sc[(hb+0)*64 + jj] = s0 * SCALE;
        sc[(hb+1)*64 + jj] = s1 * SCALE;
        sc[(hb+2)*64 + jj] = s2 * SCALE;
        sc[(hb+3)*64 + jj] = s3 * SCALE;
    } else {
        sc[(hb+0)*64 + jj] = NEGF;
        sc[(hb+1)*64 + jj] = NEGF;
        sc[(hb+2)*64 + jj] = NEGF;
        sc[(hb+3)*64 + jj] = NEGF;
    }
}

__device__ __forceinline__ void attn_softmax_update(
    float* sc, float* mS, float* lS, float* fS, int tid)
{
    int h = tid >> 4, t = tid & 15;
    float4 sv = *(float4*)&sc[h*64 + t*4];
    float pm = fmaxf(fmaxf(sv.x, sv.y), fmaxf(sv.z, sv.w));
#pragma unroll
    for (int o = 1; o < 16; o <<= 1) pm = fmaxf(pm, __shfl_xor_sync(0xffffffff, pm, o));
    float mOld = mS[h];
    float mNew = fmaxf(mOld, pm);
    float4 p;
    p.x = __expf(sv.x - mNew); p.y = __expf(sv.y - mNew);
    p.z = __expf(sv.z - mNew); p.w = __expf(sv.w - mNew);
    *(float4*)&sc[h*64 + t*4] = p;
    float ps = p.x + p.y + p.z + p.w;
#pragma unroll
    for (int o = 1; o < 16; o <<= 1) ps += __shfl_xor_sync(0xffffffff, ps, o);
    if (t == 0) {
        float f = __expf(mOld - mNew);
        fS[h] = f;
        lS[h] = lS[h] * f + ps;
        mS[h] = mNew;
    }
}

// PV accumulate: thread owns (head h, d-slice d0..d0+7)
__device__ __forceinline__ void attn_pv(
    const float* kv, const float* sc, float* acc, float f, int h, int d0, int tl)
{
#pragma unroll
    for (int i = 0; i < 8; i++) acc[i] *= f;
    for (int j = 0; j < tl; j++) {
        float p = sc[h*64 + j];
        float4 v0 = *(const float4*)&kv[j*KVP + d0];
        float4 v1 = *(const float4*)&kv[j*KVP + d0 + 4];
        acc[0] += p*v0.x; acc[1] += p*v0.y; acc[2] += p*v0.z; acc[3] += p*v0.w;
        acc[4] += p*v1.x; acc[5] += p*v1.y; acc[6] += p*v1.z; acc[7] += p*v1.w;
    }
}

// ---------------- sliding-window attention (all heads per token) ------------
__global__ void __launch_bounds__(256, 2)
win_attn_kernel(const float* __restrict__ q, const float* __restrict__ k,
                const float* __restrict__ v, float* __restrict__ out)
{
    int n = blockIdx.x;
    int tid = threadIdx.x;
    __shared__ float qs[HQ*D];
    __shared__ float kv[64*KVP];
    __shared__ float sc[HQ*64];
    __shared__ float mS[HQ], lS[HQ], fS[HQ];

    int lo  = n - WIN; if (lo < 0) lo = 0;
    int cnt = n - lo + 1;

    for (int e = tid; e < HQ*D/4; e += 256)
        ((float4*)qs)[e] = ((const float4*)(q + (size_t)n*HQ*D))[e];
    if (tid < HQ) { mS[tid] = -FLT_MAX; lS[tid] = 0.f; }

    int h  = tid >> 4;
    int d0 = (tid & 15) * 8;
    float acc[8];
#pragma unroll
    for (int i = 0; i < 8; i++) acc[i] = 0.f;
    __syncthreads();

    for (int t0 = 0; t0 < cnt; t0 += 64) {
        int tl = cnt - t0; if (tl > 64) tl = 64;
        for (int e = tid; e < 64*32; e += 256) {
            int row = e >> 5, c = e & 31;
            if (row < tl)
                *(float4*)&kv[row*KVP + c*4] = ((const float4*)(k + (size_t)(lo + t0 + row)*D))[c];
        }
        __syncthreads();
        attn_tile_scores(qs, kv, sc, tid, tl);
        __syncthreads();
        attn_softmax_update(sc, mS, lS, fS, tid);
        __syncthreads();
        for (int e = tid; e < 64*32; e += 256) {
            int row = e >> 5, c = e & 31;
            if (row < tl)
                *(float4*)&kv[row*KVP + c*4] = ((const float4*)(v + (size_t)(lo + t0 + row)*D))[c];
        }
        __syncthreads();
        attn_pv(kv, sc, acc, fS[h], h, d0, tl);
        __syncthreads();
    }
    float inv = 1.f / lS[h];
    float4 o0 = make_float4(acc[0]*inv, acc[1]*inv, acc[2]*inv, acc[3]*inv);
    float4 o1 = make_float4(acc[4]*inv, acc[5]*inv, acc[6]*inv, acc[7]*inv);
    *(float4*)&out[((size_t)n*HQ + h)*D + d0]     = o0;
    *(float4*)&out[((size_t)n*HQ + h)*D + d0 + 4] = o1;
}

// ---------------- selected (top-k) attention (all heads per token) ----------
__global__ void __launch_bounds__(256, 2)
sel_attn_kernel(const float* __restrict__ q, const float* __restrict__ k,
                const float* __restrict__ v, const int* __restrict__ topk,
                float* __restrict__ out)
{
    int n = blockIdx.x;
    int tid = threadIdx.x;
    __shared__ float qs[HQ*D];
    __shared__ float kv[64*KVP];
    __shared__ float sc[HQ*64];
    __shared__ int   posA[TOPK*BSZ];
    __shared__ float mS[HQ], lS[HQ], fS[HQ];

    for (int e = tid; e < HQ*D/4; e += 256)
        ((float4*)qs)[e] = ((const float4*)(q + (size_t)n*HQ*D))[e];
    if (tid < HQ) { mS[tid] = -FLT_MAX; lS[tid] = 0.f; }
    posA[tid] = topk[n*TOPK + (tid >> 5)] * BSZ + (tid & 31);

    int h  = tid >> 4;
    int d0 = (tid & 15) * 8;
    float acc[8];
#pragma unroll
    for (int i = 0; i < 8; i++) acc[i] = 0.f;
    __syncthreads();

    for (int t0 = 0; t0 < TOPK*BSZ; t0 += 64) {
        for (int e = tid; e < 64*32; e += 256) {
            int row = e >> 5, c = e & 31;
            *(float4*)&kv[row*KVP + c*4] = ((const float4*)(k + (size_t)posA[t0 + row]*D))[c];
        }
        __syncthreads();
        {
            int jj = tid & 63;
            int hb = (tid >> 6) * 4;
            bool valid = posA[t0 + jj] <= n;
            float s0=0.f,s1=0.f,s2=0.f,s3=0.f;
            if (valid) {
                const float4* kr = (const float4*)(kv + jj*KVP);
                const float4* q0 = (const float4*)(qs + (hb+0)*D);
                const float4* q1 = (const float4*)(qs + (hb+1)*D);
                const float4* q2 = (const float4*)(qs + (hb+2)*D);
                const float4* q3 = (const float4*)(qs + (hb+3)*D);
#pragma unroll
                for (int c = 0; c < 32; c++) {
                    float4 kk = kr[c];
                    float4 a;
                    a = q0[c]; s0 += a.x*kk.x + a.y*kk.y + a.z*kk.z + a.w*kk.w;
                    a = q1[c]; s1 += a.x*kk.x + a.y*kk.y + a.z*kk.z + a.w*kk.w;
                    a = q2[c]; s2 += a.x*kk.x + a.y*kk.y + a.z*kk.z + a.w*kk.w;
                    a = q3[c]; s3 += a.x*kk.x + a.y*kk.y + a.z*kk.z + a.w*kk.w;
                }
                sc[(hb+0)*64+jj]=s0*SCALE; sc[(hb+1)*64+jj]=s1*SCALE;
                sc[(hb+2)*64+jj]=s2*SCALE; sc[(hb+3)*64+jj]=s3*SCALE;
            } else {
                sc[(hb+0)*64+jj]=NEGF; sc[(hb+1)*64+jj]=NEGF;
                sc[(hb+2)*64+jj]=NEGF; sc[(hb+3)*64+jj]=NEGF;
            }
        }
        __syncthreads();
        attn_softmax_update(sc, mS, lS, fS, tid);
        __syncthreads();
        for (int e = tid; e < 64*32; e += 256) {
            int row = e >> 5, c = e & 31;
            *(float4*)&kv[row*KVP + c*4] = ((const float4*)(v + (size_t)posA[t0 + row]*D))[c];
        }
        __syncthreads();
        attn_pv(kv, sc, acc, fS[h], h, d0, 64);
        __syncthreads();
    }
    float inv = 1.f / lS[h];
    float4 o0 = make_float4(acc[0]*inv, acc[1]*inv, acc[2]*inv, acc[3]*inv);
    float4 o1 = make_float4(acc[4]*inv, acc[5]*inv, acc[6]*inv, acc[7]*inv);
    *(float4*)&out[((size_t)n*HQ + h)*D + d0]     = o0;
    *(float4*)&out[((size_t)n*HQ + h)*D + d0 + 4] = o1;
}

// ---------------- gate combine ---------------------------------------------
__global__ void combine_kernel(const float* __restrict__ gbuf,
                               const float* __restrict__ cmp,
                               const float* __restrict__ sp,
                               const float* __restrict__ sw,
                               float* __restrict__ att)
{
    size_t idx = (size_t)blockIdx.x * 256 + threadIdx.x;
    int n = (int)(idx >> 11);
    int hd = (int)(idx & 2047);
    int h = hd >> 7;
    const float* g = gbuf + (size_t)n*HQ*3 + h*3;
    float g0 = 1.f / (1.f + __expf(-g[0]));
    float g1 = 1.f / (1.f + __expf(-g[1]));
    float g2 = 1.f / (1.f + __expf(-g[2]));
    att[idx] = g0 * cmp[idx] + g1 * sp[idx] + g2 * sw[idx];
}

// ---------------- launcher --------------------------------------------------
extern "C" void kernel_launch(void* const* d_in, const int* in_sizes, int n_in,
                              void* d_out, int out_size)
{
    const float* x  = (const float*)d_in[0];
    const float* Wq = (const float*)d_in[2];
    const float* Wk = (const float*)d_in[3];
    const float* Wv = (const float*)d_in[4];
    const float* Wo = (const float*)d_in[5];
    const float* Wg = (const float*)d_in[6];
    const float* pe = (const float*)d_in[7];
    float* out = (float*)d_out;

    float *q, *k, *v, *ck, *cv, *blks, *cmp, *sp, *sw, *gate, *att, *part;
    int* tk;
    cudaGetSymbolAddress((void**)&q,    g_q);
    cudaGetSymbolAddress((void**)&k,    g_k);
    cudaGetSymbolAddress((void**)&v,    g_v);
    cudaGetSymbolAddress((void**)&ck,   g_ck);
    cudaGetSymbolAddress((void**)&cv,   g_cv);
    cudaGetSymbolAddress((void**)&blks, g_blks);
    cudaGetSymbolAddress((void**)&tk,   g_topk);
    cudaGetSymbolAddress((void**)&cmp,  g_cmp);
    cudaGetSymbolAddress((void**)&sp,   g_sp);
    cudaGetSymbolAddress((void**)&sw,   g_sw);
    cudaGetSymbolAddress((void**)&gate, g_gate);
    cudaGetSymbolAddress((void**)&att,  g_att);
    cudaGetSymbolAddress((void**)&part, g_part);

    // big projections
    gemm_tf32x3_kernel<<<dim3(32, 16, 1), 256>>>(x, Wq, q, nullptr, HID, HQ*D);

    // narrow projections: split-K=8 + reduce
    gemm_tf32x3_kernel<<<dim3(2, 16, 8), 256>>>(x, Wk, k, part, HID, D);
    splitk_reduce_kernel<<<(N_TOK*D + 255)/256, 256>>>(part, k, N_TOK*D, 8);
    gemm_tf32x3_kernel<<<dim3(2, 16, 8), 256>>>(x, Wv, v, part, HID, D);
    splitk_reduce_kernel<<<(N_TOK*D + 255)/256, 256>>>(part, v, N_TOK*D, 8);
    gemm_tf32x3_kernel<<<dim3(1, 16, 8), 256>>>(x, Wg, gate, part, HID, HQ*3);
    splitk_reduce_kernel<<<(N_TOK*HQ*3 + 255)/256, 256>>>(part, gate, N_TOK*HQ*3, 8);

    // compress (pre-RoPE k), then RoPE
    compress_kernel<<<NC, D>>>(k, v, pe, ck, cv);
    rope_kernel<<<N_TOK, 64>>>(q, HQ, 1);
    rope_kernel<<<N_TOK, 64>>>(k, 1, 1);
    rope_kernel<<<NC, 64>>>(ck, 1, STRIDE);

    // branches
    cmp_attn_kernel<<<N_TOK, 256>>>(q, ck, cv, cmp, blks);
    topk_kernel<<<N_TOK/256, 256>>>(blks, tk);
    sel_attn_kernel<<<N_TOK, 256>>>(q, k, v, tk, sp);
    win_attn_kernel<<<N_TOK, 256>>>(q, k, v, sw);

    // gate combine + output projection
    combine_kernel<<<(N_TOK*HQ*D)/256, 256>>>(gate, cmp, sp, sw, att);
    gemm_tf32x3_kernel<<<dim3(32, 16, 1), 256>>>(att, Wo, out, nullptr, HID, HID);
}

// round 5
// speedup vs baseline: 4.3770x; 1.0381x over previous
#include <cuda_runtime.h>
#include <cuda_bf16.h>
#include <math.h>
#include <float.h>
#include <stdint.h>

#define N_TOK 2048
#define HID   2048
#define HQ    16
#define D     128
#define NC    64
#define KS    32
#define STRIDE 32
#define BSZ   32
#define TOPK  8
#define WIN   512
#define SCALE 0.08838834764831845f  /* 1/sqrt(128) */
#define NEGF  -1e30f

// ---------------- scratch (device globals) ---------------------------------
__device__ float g_q   [N_TOK*HQ*D];
__device__ float g_k   [N_TOK*D];
__device__ float g_v   [N_TOK*D];
__device__ float g_ck  [NC*D];
__device__ float g_cv  [NC*D];
__device__ float g_blks[N_TOK*NC];
__device__ int   g_topk[N_TOK*TOPK];
__device__ float g_cmp [N_TOK*HQ*D];
__device__ float g_sp  [N_TOK*HQ*D];
__device__ float g_sw  [N_TOK*HQ*D];
__device__ float g_gate[N_TOK*HQ*3];
__device__ float g_att [N_TOK*HID];
__device__ float g_part[8 * N_TOK * 128];   // split-K partials (max M=128)

// ---------------- tf32 helpers ----------------------------------------------
__device__ __forceinline__ uint32_t f2tf32(float f) {
    uint32_t u;
    asm("cvt.rna.tf32.f32 %0, %1;" : "=r"(u) : "f"(f));
    return u;
}
__device__ __forceinline__ void mma_tf32(float* c, const uint32_t* a,
                                         uint32_t b0, uint32_t b1) {
    asm volatile(
        "mma.sync.aligned.m16n8k8.row.col.f32.tf32.tf32.f32 "
        "{%0,%1,%2,%3}, {%4,%5,%6,%7}, {%8,%9}, {%0,%1,%2,%3};"
        : "+f"(c[0]), "+f"(c[1]), "+f"(c[2]), "+f"(c[3])
        : "r"(a[0]), "r"(a[1]), "r"(a[2]), "r"(a[3]), "r"(b0), "r"(b1));
}

// ---------------- tf32 GEMM v3 ----------------------------------------------
// C[2048, M] = A[2048, K] @ B[K, M]. Block tile 128x128xBK16, 8 warps (2m x 4n),
// warp tile 64x32. Pair-packed smem {k, k+4} as uint2, XOR swizzle -> LDS.64
// conflict-free. Double-buffered. TERMS=3: Ootomo hi/lo split (fp32-accurate);
// TERMS=1: plain tf32.
template<int TERMS>
__global__ void __launch_bounds__(256, 2)
gemm_kernel(const float* __restrict__ A, const float* __restrict__ B,
            float* __restrict__ C, float* __restrict__ Cpart, int K, int M)
{
    extern __shared__ uint2 sm[];
    uint2* AsH = sm;               // [2][128][8]
    uint2* BsH = sm + 2048;        // [2][128][8]
    uint2* AsL = sm + 4096;        // TERMS==3 only
    uint2* BsL = sm + 6144;

    const int tid = threadIdx.x;
    const int wid = tid >> 5, lane = tid & 31;
    const int row0 = blockIdx.y * 128, col0 = blockIdx.x * 128;
    const int wr = (wid & 1) * 64, wc = (wid >> 1) * 32;
    const int g = lane >> 2, tg = lane & 3;
    const int S = gridDim.z, Kc = K / S, kbeg = blockIdx.z * Kc;

    // loader coords: A: 128 rows x 16 k (8 floats/thread); B: 16 k x 128 cols
    const int arow = tid >> 1, akb = (tid & 1) * 8;
    const int bkrow = tid >> 4, bcol = (tid & 15) * 8;
    const bool bval0 = (col0 + bcol + 4) <= M;
    const bool bval1 = (col0 + bcol + 8) <= M;

    const float* Ag = A + (size_t)(row0 + arow) * K + akb;
    const float* Bg = B + (size_t)bkrow * M + col0 + bcol;

    float acc[4][4][4];
#pragma unroll
    for (int mt = 0; mt < 4; mt++)
#pragma unroll
        for (int ni = 0; ni < 4; ni++)
#pragma unroll
            for (int r = 0; r < 4; r++) acc[mt][ni][r] = 0.f;

    float av[8], bb[8];

    auto loadG = [&](int k0) {
        float4 t0 = *(const float4*)(Ag + k0);
        float4 t1 = *(const float4*)(Ag + k0 + 4);
        av[0]=t0.x; av[1]=t0.y; av[2]=t0.z; av[3]=t0.w;
        av[4]=t1.x; av[5]=t1.y; av[6]=t1.z; av[7]=t1.w;
        const float* bp = Bg + (size_t)k0 * M;
        float4 u0 = bval0 ? *(const float4*)bp       : make_float4(0,0,0,0);
        float4 u1 = bval1 ? *(const float4*)(bp + 4) : make_float4(0,0,0,0);
        bb[0]=u0.x; bb[1]=u0.y; bb[2]=u0.z; bb[3]=u0.w;
        bb[4]=u1.x; bb[5]=u1.y; bb[6]=u1.z; bb[7]=u1.w;
    };

    auto storeS = [&](int st) {
        const int sbase = st << 10;
#pragma unroll
        for (int u = 0; u < 8; u++) {
            int k = akb + u;
            int p = ((k >> 3) << 2) | (k & 3);
            int c = (k >> 2) & 1;
            int ph = p ^ ((arow & 3) << 1);
            uint32_t hi = f2tf32(av[u]);
            ((uint32_t*)&AsH[sbase + (arow << 3) + ph])[c] = hi;
            if (TERMS == 3) {
                uint32_t lo = f2tf32(av[u] - __uint_as_float(hi));
                ((uint32_t*)&AsL[sbase + (arow << 3) + ph])[c] = lo;
            }
        }
        {
            int k = bkrow;
            int p = ((k >> 3) << 2) | (k & 3);
            int c = (k >> 2) & 1;
#pragma unroll
            for (int u = 0; u < 8; u++) {
                int col = bcol + u;
                int ph = p ^ ((col & 3) << 1);
                uint32_t hi = f2tf32(bb[u]);
                ((uint32_t*)&BsH[sbase + (col << 3) + ph])[c] = hi;
                if (TERMS == 3) {
                    uint32_t lo = f2tf32(bb[u] - __uint_as_float(hi));
                    ((uint32_t*)&BsL[sbase + (col << 3) + ph])[c] = lo;
                }
            }
        }
    };

    auto compute = [&](int st) {
        const int sbase = st << 10;
#pragma unroll
        for (int hb = 0; hb < 2; hb++) {
            const int ph = (hb * 4 + tg) ^ ((g & 3) << 1);
            uint32_t afH[4][4];
            uint2 bH[4];
#pragma unroll
            for (int mt = 0; mt < 4; mt++) {
                int r = wr + mt * 16 + g;
                uint2 p0 = AsH[sbase + (r << 3) + ph];
                uint2 p1 = AsH[sbase + ((r + 8) << 3) + ph];
                afH[mt][0] = p0.x; afH[mt][1] = p1.x;
                afH[mt][2] = p0.y; afH[mt][3] = p1.y;
            }
#pragma unroll
            for (int ni = 0; ni < 4; ni++) {
                int cc = wc + ni * 8 + g;
                bH[ni] = BsH[sbase + (cc << 3) + ph];
            }
            // term 1: hi*hi
#pragma unroll
            for (int ni = 0; ni < 4; ni++)
#pragma unroll
                for (int mt = 0; mt < 4; mt++)
                    mma_tf32(acc[mt][ni], afH[mt], bH[ni].x, bH[ni].y);
            if (TERMS == 3) {
                // term 2: hi * loB
                uint2 bL[4];
#pragma unroll
                for (int ni = 0; ni < 4; ni++) {
                    int cc = wc + ni * 8 + g;
                    bL[ni] = BsL[sbase + (cc << 3) + ph];
                }
#pragma unroll
                for (int ni = 0; ni < 4; ni++)
#pragma unroll
                    for (int mt = 0; mt < 4; mt++)
                        mma_tf32(acc[mt][ni], afH[mt], bL[ni].x, bL[ni].y);
                // term 3: loA * hi (per-mt reload to cap registers)
#pragma unroll
                for (int mt = 0; mt < 4; mt++) {
                    int r = wr + mt * 16 + g;
                    uint2 p0 = AsL[sbase + (r << 3) + ph];
                    uint2 p1 = AsL[sbase + ((r + 8) << 3) + ph];
                    uint32_t afL[4] = {p0.x, p1.x, p0.y, p1.y};
#pragma unroll
                    for (int ni = 0; ni < 4; ni++)
                        mma_tf32(acc[mt][ni], afL, bH[ni].x, bH[ni].y);
                }
            }
        }
    };

    // prologue
    loadG(kbeg);
    storeS(0);
    __syncthreads();

    const int nIter = Kc >> 4;
    for (int it = 0; it < nIter; it++) {
        int st = it & 1;
        bool hasNext = (it + 1 < nIter);
        if (hasNext) loadG(kbeg + (it + 1) * 16);
        compute(st);
        if (hasNext) storeS(st ^ 1);
        __syncthreads();
    }

    float* Cout = (S == 1) ? C : (Cpart + (size_t)blockIdx.z * N_TOK * M);
#pragma unroll
    for (int mt = 0; mt < 4; mt++) {
#pragma unroll
        for (int ni = 0; ni < 4; ni++) {
            int r = row0 + wr + mt * 16 + g;
            int c = col0 + wc + ni * 8 + tg * 2;
            if (c + 2 <= M) {
                *(float2*)&Cout[(size_t)r * M + c] =
                    make_float2(acc[mt][ni][0], acc[mt][ni][1]);
                *(float2*)&Cout[(size_t)(r + 8) * M + c] =
                    make_float2(acc[mt][ni][2], acc[mt][ni][3]);
            }
        }
    }
}

// sum split-K partials
__global__ void splitk_reduce_kernel(const float* __restrict__ part,
                                     float* __restrict__ out, int len, int S)
{
    int i = blockIdx.x * 256 + threadIdx.x;
    if (i >= len) return;
    float s = 0.f;
    for (int z = 0; z < S; z++) s += part[(size_t)z * len + i];
    out[i] = s;
}

// ---------------- compressed k/v (pre-RoPE) --------------------------------
__global__ void compress_kernel(const float* __restrict__ k,
                                const float* __restrict__ v,
                                const float* __restrict__ pe,
                                float* __restrict__ ck,
                                float* __restrict__ cv)
{
    int m = blockIdx.x;
    int d = threadIdx.x;
    float sk = 0.f, sv = 0.f;
#pragma unroll 8
    for (int i = 0; i < KS; i++) {
        sk += k[(m*KS + i)*D + d] + pe[i*D + d];
        sv += v[(m*KS + i)*D + d];
    }
    ck[m*D + d] = sk * (1.f/KS);
    cv[m*D + d] = sv * (1.f/KS);
}

// ---------------- RoPE (in place) ------------------------------------------
__global__ void rope_kernel(float* __restrict__ x, int heads, int pos_stride)
{
    int row = blockIdx.x;
    int d   = threadIdx.x;    // 0..63
    float inv = powf(10000.f, -(float)d / 64.f);
    float ang = (float)(row * pos_stride) * inv;
    float c = cosf(ang), s = sinf(ang);
    for (int h = 0; h < heads; h++) {
        float* p = x + ((size_t)row*heads + h) * D;
        float x1 = p[d], x2 = p[d + 64];
        p[d]      = x1 * c - x2 * s;
        p[d + 64] = x2 * c + x1 * s;
    }
}

// ---------------- compressed attention: one block per token -----------------
__global__ void cmp_attn_kernel(const float* __restrict__ q,
                                const float* __restrict__ ck,
                                const float* __restrict__ cv,
                                float* __restrict__ out,
                                float* __restrict__ blks)
{
    int n = blockIdx.x;
    __shared__ float qs[HQ*D];
    __shared__ float pcs[HQ][NC];
    int tid = threadIdx.x;            // 256

    for (int e = tid; e < HQ*D/4; e += 256)
        ((float4*)qs)[e] = ((const float4*)(q + (size_t)n*HQ*D))[e];
    __syncthreads();

    for (int e = tid; e < HQ*NC; e += 256) {
        int h = e >> 6, m = e & (NC-1);
        float s = 0.f;
        const float* qp = qs + h*D;
        const float* cp = ck + m*D;
#pragma unroll 8
        for (int d = 0; d < D; d++) s += qp[d] * cp[d];
        s *= SCALE;
        bool valid = (n >= m*STRIDE + KS - 1);
        pcs[h][m] = valid ? s : NEGF;
    }
    __syncthreads();

    if (tid < HQ) {
        int h = tid;
        float mx = -FLT_MAX;
        for (int m = 0; m < NC; m++) mx = fmaxf(mx, pcs[h][m]);
        float sum = 0.f;
        for (int m = 0; m < NC; m++) { float e = __expf(pcs[h][m] - mx); pcs[h][m] = e; sum += e; }
        float invs = 1.f / sum;
        for (int m = 0; m < NC; m++) {
            bool valid = (n >= m*STRIDE + KS - 1);
            pcs[h][m] = valid ? pcs[h][m] * invs : 0.f;
        }
    }
    __syncthreads();

    for (int m = tid; m < NC; m += 256) {
        float s = 0.f;
        for (int h = 0; h < HQ; h++) s += pcs[h][m];
        blks[(size_t)n*NC + m] = s;
    }

    for (int e = tid; e < HQ*D; e += 256) {
        int h = e >> 7, d = e & (D-1);
        float a = 0.f;
#pragma unroll 4
        for (int m = 0; m < NC; m++) a += pcs[h][m] * cv[m*D + d];
        out[(size_t)n*HQ*D + e] = a;
    }
}

// ---------------- top-k selection ------------------------------------------
__global__ void topk_kernel(const float* __restrict__ blks, int* __restrict__ topk)
{
    int n = blockIdx.x * blockDim.x + threadIdx.x;
    if (n >= N_TOK) return;
    float sel[NC];
    int tb = n / BSZ;
    for (int m = 0; m < NC; m++) {
        float s = blks[(size_t)n*NC + m];
        if (m > tb) s = NEGF;
        if (m < 1 || (m <= tb && m > tb - 2)) s = 1e30f;
        sel[m] = s;
    }
    for (int j = 0; j < TOPK; j++) {
        int bi = 0; float bv = sel[0];
        for (int m = 1; m < NC; m++) if (sel[m] > bv) { bv = sel[m]; bi = m; }
        topk[n*TOPK + j] = bi;
        sel[bi] = -FLT_MAX;
    }
}

// ============ flash-style attention helpers =================================
#define KVP 132

__device__ __forceinline__ void attn_tile_scores(
    const float* qs, const float* kv, float* sc, int tid, int tl)
{
    int jj = tid & 63;
    int hb = (tid >> 6) * 4;
    float s0 = 0.f, s1 = 0.f, s2 = 0.f, s3 = 0.f;
    if (jj < tl) {
        const float4* kr = (const float4*)(kv + jj * KVP);
        const float4* q0 = (const float4*)(qs + (hb+0) * D);
        const float4* q1 = (const float4*)(qs + (hb+1) * D);
        const float4* q2 = (const float4*)(qs + (hb+2) * D);
        const float4* q3 = (const float4*)(qs + (hb+3) * D);
#pragma unroll
        for (int c = 0; c < 32; c++) {
            float4 kk = kr[c];
            float4 a;
            a = q0[c]; s0 += a.x*kk.x + a.y*kk.y + a.z*kk.z + a.w*kk.w;
            a = q1[c]; s1 += a.x*kk.x + a.y*kk.y + a.z*kk.z + a.w*kk.w;
            a = q2[c]; s2 += a.x*kk.x + a.y*kk.y + a.z*kk.z + a.w*kk.w;
            a = q3[c]; s3 += a.x*kk.x + a.y*kk.y + a.z*kk.z + a.w*kk.w;
        }
        sc[(hb+0)*64 + jj] = s0 * SCALE;
        sc[(hb+1)*64 + jj] = s1 * SCALE;
        sc[(hb+2)*64 + jj] = s2 * SCALE;
        sc[(hb+3)*64 + jj] = s3 * SCALE;
    } else {
        sc[(hb+0)*64 + jj] = NEGF;
        sc[(hb+1)*64 + jj] = NEGF;
        sc[(hb+2)*64 + jj] = NEGF;
        sc[(hb+3)*64 + jj] = NEGF;
    }
}

__device__ __forceinline__ void attn_softmax_update(
    float* sc, float* mS, float* lS, float* fS, int tid)
{
    int h = tid >> 4, t = tid & 15;
    float4 sv = *(float4*)&sc[h*64 + t*4];
    float pm = fmaxf(fmaxf(sv.x, sv.y), fmaxf(sv.z, sv.w));
#pragma unroll
    for (int o = 1; o < 16; o <<= 1) pm = fmaxf(pm, __shfl_xor_sync(0xffffffff, pm, o));
    float mOld = mS[h];
    float mNew = fmaxf(mOld, pm);
    float4 p;
    p.x = __expf(sv.x - mNew); p.y = __expf(sv.y - mNew);
    p.z = __expf(sv.z - mNew); p.w = __expf(sv.w - mNew);
    *(float4*)&sc[h*64 + t*4] = p;
    float ps = p.x + p.y + p.z + p.w;
#pragma unroll
    for (int o = 1; o < 16; o <<= 1) ps += __shfl_xor_sync(0xffffffff, ps, o);
    if (t == 0) {
        float f = __expf(mOld - mNew);
        fS[h] = f;
        lS[h] = lS[h] * f + ps;
        mS[h] = mNew;
    }
}

// PV accumulate: thread owns (head h, d-slice d0..d0+7)
__device__ __forceinline__ void attn_pv(
    const float* kv, const float* sc, float* acc, float f, int h, int d0, int tl)
{
#pragma unroll
    for (int i = 0; i < 8; i++) acc[i] *= f;
    for (int j = 0; j < tl; j++) {
        float p = sc[h*64 + j];
        float4 v0 = *(const float4*)&kv[j*KVP + d0];
        float4 v1 = *(const float4*)&kv[j*KVP + d0 + 4];
        acc[0] += p*v0.x; acc[1] += p*v0.y; acc[2] += p*v0.z; acc[3] += p*v0.w;
        acc[4] += p*v1.x; acc[5] += p*v1.y; acc[6] += p*v1.z; acc[7] += p*v1.w;
    }
}

// ---------------- sliding-window attention (all heads per token) ------------
__global__ void __launch_bounds__(256, 2)
win_attn_kernel(const float* __restrict__ q, const float* __restrict__ k,
                const float* __restrict__ v, float* __restrict__ out)
{
    int n = blockIdx.x;
    int tid = threadIdx.x;
    __shared__ float qs[HQ*D];
    __shared__ float kv[64*KVP];
    __shared__ float sc[HQ*64];
    __shared__ float mS[HQ], lS[HQ], fS[HQ];

    int lo  = n - WIN; if (lo < 0) lo = 0;
    int cnt = n - lo + 1;

    for (int e = tid; e < HQ*D/4; e += 256)
        ((float4*)qs)[e] = ((const float4*)(q + (size_t)n*HQ*D))[e];
    if (tid < HQ) { mS[tid] = -FLT_MAX; lS[tid] = 0.f; }

    int h  = tid >> 4;
    int d0 = (tid & 15) * 8;
    float acc[8];
#pragma unroll
    for (int i = 0; i < 8; i++) acc[i] = 0.f;
    __syncthreads();

    for (int t0 = 0; t0 < cnt; t0 += 64) {
        int tl = cnt - t0; if (tl > 64) tl = 64;
        for (int e = tid; e < 64*32; e += 256) {
            int row = e >> 5, c = e & 31;
            if (row < tl)
                *(float4*)&kv[row*KVP + c*4] = ((const float4*)(k + (size_t)(lo + t0 + row)*D))[c];
        }
        __syncthreads();
        attn_tile_scores(qs, kv, sc, tid, tl);
        __syncthreads();
        attn_softmax_update(sc, mS, lS, fS, tid);
        __syncthreads();
        for (int e = tid; e < 64*32; e += 256) {
            int row = e >> 5, c = e & 31;
            if (row < tl)
                *(float4*)&kv[row*KVP + c*4] = ((const float4*)(v + (size_t)(lo + t0 + row)*D))[c];
        }
        __syncthreads();
        attn_pv(kv, sc, acc, fS[h], h, d0, tl);
        __syncthreads();
    }
    float inv = 1.f / lS[h];
    float4 o0 = make_float4(acc[0]*inv, acc[1]*inv, acc[2]*inv, acc[3]*inv);
    float4 o1 = make_float4(acc[4]*inv, acc[5]*inv, acc[6]*inv, acc[7]*inv);
    *(float4*)&out[((size_t)n*HQ + h)*D + d0]     = o0;
    *(float4*)&out[((size_t)n*HQ + h)*D + d0 + 4] = o1;
}

// ---------------- selected (top-k) attention (all heads per token) ----------
__global__ void __launch_bounds__(256, 2)
sel_attn_kernel(const float* __restrict__ q, const float* __restrict__ k,
                const float* __restrict__ v, const int* __restrict__ topk,
                float* __restrict__ out)
{
    int n = blockIdx.x;
    int tid = threadIdx.x;
    __shared__ float qs[HQ*D];
    __shared__ float kv[64*KVP];
    __shared__ float sc[HQ*64];
    __shared__ int   posA[TOPK*BSZ];
    __shared__ float mS[HQ], lS[HQ], fS[HQ];

    for (int e = tid; e < HQ*D/4; e += 256)
        ((float4*)qs)[e] = ((const float4*)(q + (size_t)n*HQ*D))[e];
    if (tid < HQ) { mS[tid] = -FLT_MAX; lS[tid] = 0.f; }
    posA[tid] = topk[n*TOPK + (tid >> 5)] * BSZ + (tid & 31);

    int h  = tid >> 4;
    int d0 = (tid & 15) * 8;
    float acc[8];
#pragma unroll
    for (int i = 0; i < 8; i++) acc[i] = 0.f;
    __syncthreads();

    for (int t0 = 0; t0 < TOPK*BSZ; t0 += 64) {
        for (int e = tid; e < 64*32; e += 256) {
            int row = e >> 5, c = e & 31;
            *(float4*)&kv[row*KVP + c*4] = ((const float4*)(k + (size_t)posA[t0 + row]*D))[c];
        }
        __syncthreads();
        {
            int jj = tid & 63;
            int hb = (tid >> 6) * 4;
            bool valid = posA[t0 + jj] <= n;
            float s0=0.f,s1=0.f,s2=0.f,s3=0.f;
            if (valid) {
                const float4* kr = (const float4*)(kv + jj*KVP);
                const float4* q0 = (const float4*)(qs + (hb+0)*D);
                const float4* q1 = (const float4*)(qs + (hb+1)*D);
                const float4* q2 = (const float4*)(qs + (hb+2)*D);
                const float4* q3 = (const float4*)(qs + (hb+3)*D);
#pragma unroll
                for (int c = 0; c < 32; c++) {
                    float4 kk = kr[c];
                    float4 a;
                    a = q0[c]; s0 += a.x*kk.x + a.y*kk.y + a.z*kk.z + a.w*kk.w;
                    a = q1[c]; s1 += a.x*kk.x + a.y*kk.y + a.z*kk.z + a.w*kk.w;
                    a = q2[c]; s2 += a.x*kk.x + a.y*kk.y + a.z*kk.z + a.w*kk.w;
                    a = q3[c]; s3 += a.x*kk.x + a.y*kk.y + a.z*kk.z + a.w*kk.w;
                }
                sc[(hb+0)*64+jj]=s0*SCALE; sc[(hb+1)*64+jj]=s1*SCALE;
                sc[(hb+2)*64+jj]=s2*SCALE; sc[(hb+3)*64+jj]=s3*SCALE;
            } else {
                sc[(hb+0)*64+jj]=NEGF; sc[(hb+1)*64+jj]=NEGF;
                sc[(hb+2)*64+jj]=NEGF; sc[(hb+3)*64+jj]=NEGF;
            }
        }
        __syncthreads();
        attn_softmax_update(sc, mS, lS, fS, tid);
        __syncthreads();
        for (int e = tid; e < 64*32; e += 256) {
            int row = e >> 5, c = e & 31;
            *(float4*)&kv[row*KVP + c*4] = ((const float4*)(v + (size_t)posA[t0 + row]*D))[c];
        }
        __syncthreads();
        attn_pv(kv, sc, acc, fS[h], h, d0, 64);
        __syncthreads();
    }
    float inv = 1.f / lS[h];
    float4 o0 = make_float4(acc[0]*inv, acc[1]*inv, acc[2]*inv, acc[3]*inv);
    float4 o1 = make_float4(acc[4]*inv, acc[5]*inv, acc[6]*inv, acc[7]*inv);
    *(float4*)&out[((size_t)n*HQ + h)*D + d0]     = o0;
    *(float4*)&out[((size_t)n*HQ + h)*D + d0 + 4] = o1;
}

// ---------------- gate combine ---------------------------------------------
__global__ void combine_kernel(const float* __restrict__ gbuf,
                               const float* __restrict__ cmp,
                               const float* __restrict__ sp,
                               const float* __restrict__ sw,
                               float* __restrict__ att)
{
    size_t idx = (size_t)blockIdx.x * 256 + threadIdx.x;
    int n = (int)(idx >> 11);
    int hd = (int)(idx & 2047);
    int h = hd >> 7;
    const float* g = gbuf + (size_t)n*HQ*3 + h*3;
    float g0 = 1.f / (1.f + __expf(-g[0]));
    float g1 = 1.f / (1.f + __expf(-g[1]));
    float g2 = 1.f / (1.f + __expf(-g[2]));
    att[idx] = g0 * cmp[idx] + g1 * sp[idx] + g2 * sw[idx];
}

// ---------------- launcher --------------------------------------------------
extern "C" void kernel_launch(void* const* d_in, const int* in_sizes, int n_in,
                              void* d_out, int out_size)
{
    const float* x  = (const float*)d_in[0];
    const float* Wq = (const float*)d_in[2];
    const float* Wk = (const float*)d_in[3];
    const float* Wv = (const float*)d_in[4];
    const float* Wo = (const float*)d_in[5];
    const float* Wg = (const float*)d_in[6];
    const float* pe = (const float*)d_in[7];
    float* out = (float*)d_out;

    float *q, *k, *v, *ck, *cv, *blks, *cmp, *sp, *sw, *gate, *att, *part;
    int* tk;
    cudaGetSymbolAddress((void**)&q,    g_q);
    cudaGetSymbolAddress((void**)&k,    g_k);
    cudaGetSymbolAddress((void**)&v,    g_v);
    cudaGetSymbolAddress((void**)&ck,   g_ck);
    cudaGetSymbolAddress((void**)&cv,   g_cv);
    cudaGetSymbolAddress((void**)&blks, g_blks);
    cudaGetSymbolAddress((void**)&tk,   g_topk);
    cudaGetSymbolAddress((void**)&cmp,  g_cmp);
    cudaGetSymbolAddress((void**)&sp,   g_sp);
    cudaGetSymbolAddress((void**)&sw,   g_sw);
    cudaGetSymbolAddress((void**)&gate, g_gate);
    cudaGetSymbolAddress((void**)&att,  g_att);
    cudaGetSymbolAddress((void**)&part, g_part);

    const int SMEM3 = 65536;   // 8192 uint2
    const int SMEM1 = 32768;   // 4096 uint2
    cudaFuncSetAttribute(gemm_kernel<3>, cudaFuncAttributeMaxDynamicSharedMemorySize, SMEM3);
    cudaFuncSetAttribute(gemm_kernel<1>, cudaFuncAttributeMaxDynamicSharedMemorySize, SMEM1);

    // big projections: Wq needs fp32 accuracy (feeds top-k), Wo does not
    gemm_kernel<3><<<dim3(16, 16, 1), 256, SMEM3>>>(x, Wq, q, nullptr, HID, HQ*D);

    // narrow projections: split-K=8 + reduce (k feeds top-k -> 3-term; v 3-term)
    gemm_kernel<3><<<dim3(1, 16, 8), 256, SMEM3>>>(x, Wk, k, part, HID, D);
    splitk_reduce_kernel<<<(N_TOK*D + 255)/256, 256>>>(part, k, N_TOK*D, 8);
    gemm_kernel<3><<<dim3(1, 16, 8), 256, SMEM3>>>(x, Wv, v, part, HID, D);
    splitk_reduce_kernel<<<(N_TOK*D + 255)/256, 256>>>(part, v, N_TOK*D, 8);
    gemm_kernel<1><<<dim3(1, 16, 8), 256, SMEM1>>>(x, Wg, gate, part, HID, HQ*3);
    splitk_reduce_kernel<<<(N_TOK*HQ*3 + 255)/256, 256>>>(part, gate, N_TOK*HQ*3, 8);

    // compress (pre-RoPE k), then RoPE
    compress_kernel<<<NC, D>>>(k, v, pe, ck, cv);
    rope_kernel<<<N_TOK, 64>>>(q, HQ, 1);
    rope_kernel<<<N_TOK, 64>>>(k, 1, 1);
    rope_kernel<<<NC, 64>>>(ck, 1, STRIDE);

    // branches
    cmp_attn_kernel<<<N_TOK, 256>>>(q, ck, cv, cmp, blks);
    topk_kernel<<<N_TOK/256, 256>>>(blks, tk);
    sel_attn_kernel<<<N_TOK, 256>>>(q, k, v, tk, sp);
    win_attn_kernel<<<N_TOK, 256>>>(q, k, v, sw);

    // gate combine + output projection (single tf32 is enough here)
    combine_kernel<<<(N_TOK*HQ*D)/256, 256>>>(gate, cmp, sp, sw, att);
    gemm_kernel<1><<<dim3(16, 16, 1), 256, SMEM1>>>(att, Wo, out, nullptr, HID, HID);
}

// round 6
// speedup vs baseline: 4.6041x; 1.0519x over previous
#include <cuda_runtime.h>
#include <cuda_bf16.h>
#include <math.h>
#include <float.h>
#include <stdint.h>

#define N_TOK 2048
#define HID   2048
#define HQ    16
#define D     128
#define NC    64
#define KS    32
#define STRIDE 32
#define BSZ   32
#define TOPK  8
#define WIN   512
#define SCALE 0.08838834764831845f  /* 1/sqrt(128) */
#define NEGF  -1e30f

// ---------------- scratch (device globals) ---------------------------------
__device__ float g_q   [N_TOK*HQ*D];
__device__ float g_k   [N_TOK*D];
__device__ float g_v   [N_TOK*D];
__device__ float g_ck  [NC*D];
__device__ float g_cv  [NC*D];
__device__ float g_blks[N_TOK*NC];
__device__ int   g_topk[N_TOK*TOPK];
__device__ float g_cmp [N_TOK*HQ*D];
__device__ float g_sp  [N_TOK*HQ*D];
__device__ float g_sw  [N_TOK*HQ*D];
__device__ float g_gate[N_TOK*HQ*3];
__device__ float g_att [N_TOK*HID];
__device__ float g_part[8 * N_TOK * 128];   // split-K partials (max M=128)

// ---------------- tf32 helpers ----------------------------------------------
__device__ __forceinline__ uint32_t f2tf32(float f) {
    uint32_t u;
    asm("cvt.rna.tf32.f32 %0, %1;" : "=r"(u) : "f"(f));
    return u;
}
__device__ __forceinline__ void mma_tf32(float* c, const uint32_t* a,
                                         uint32_t b0, uint32_t b1) {
    asm volatile(
        "mma.sync.aligned.m16n8k8.row.col.f32.tf32.tf32.f32 "
        "{%0,%1,%2,%3}, {%4,%5,%6,%7}, {%8,%9}, {%0,%1,%2,%3};"
        : "+f"(c[0]), "+f"(c[1]), "+f"(c[2]), "+f"(c[3])
        : "r"(a[0]), "r"(a[1]), "r"(a[2]), "r"(a[3]), "r"(b0), "r"(b1));
}

// ---------------- tf32 GEMM (as round 5) ------------------------------------
template<int TERMS>
__global__ void __launch_bounds__(256, 2)
gemm_kernel(const float* __restrict__ A, const float* __restrict__ B,
            float* __restrict__ C, float* __restrict__ Cpart, int K, int M)
{
    extern __shared__ uint2 sm[];
    uint2* AsH = sm;
    uint2* BsH = sm + 2048;
    uint2* AsL = sm + 4096;
    uint2* BsL = sm + 6144;

    const int tid = threadIdx.x;
    const int wid = tid >> 5, lane = tid & 31;
    const int row0 = blockIdx.y * 128, col0 = blockIdx.x * 128;
    const int wr = (wid & 1) * 64, wc = (wid >> 1) * 32;
    const int g = lane >> 2, tg = lane & 3;
    const int S = gridDim.z, Kc = K / S, kbeg = blockIdx.z * Kc;

    const int arow = tid >> 1, akb = (tid & 1) * 8;
    const int bkrow = tid >> 4, bcol = (tid & 15) * 8;
    const bool bval0 = (col0 + bcol + 4) <= M;
    const bool bval1 = (col0 + bcol + 8) <= M;

    const float* Ag = A + (size_t)(row0 + arow) * K + akb;
    const float* Bg = B + (size_t)bkrow * M + col0 + bcol;

    float acc[4][4][4];
#pragma unroll
    for (int mt = 0; mt < 4; mt++)
#pragma unroll
        for (int ni = 0; ni < 4; ni++)
#pragma unroll
            for (int r = 0; r < 4; r++) acc[mt][ni][r] = 0.f;

    float av[8], bb[8];

    auto loadG = [&](int k0) {
        float4 t0 = *(const float4*)(Ag + k0);
        float4 t1 = *(const float4*)(Ag + k0 + 4);
        av[0]=t0.x; av[1]=t0.y; av[2]=t0.z; av[3]=t0.w;
        av[4]=t1.x; av[5]=t1.y; av[6]=t1.z; av[7]=t1.w;
        const float* bp = Bg + (size_t)k0 * M;
        float4 u0 = bval0 ? *(const float4*)bp       : make_float4(0,0,0,0);
        float4 u1 = bval1 ? *(const float4*)(bp + 4) : make_float4(0,0,0,0);
        bb[0]=u0.x; bb[1]=u0.y; bb[2]=u0.z; bb[3]=u0.w;
        bb[4]=u1.x; bb[5]=u1.y; bb[6]=u1.z; bb[7]=u1.w;
    };

    auto storeS = [&](int st) {
        const int sbase = st << 10;
#pragma unroll
        for (int u = 0; u < 8; u++) {
            int k = akb + u;
            int p = ((k >> 3) << 2) | (k & 3);
            int c = (k >> 2) & 1;
            int ph = p ^ ((arow & 3) << 1);
            uint32_t hi = f2tf32(av[u]);
            ((uint32_t*)&AsH[sbase + (arow << 3) + ph])[c] = hi;
            if (TERMS == 3) {
                uint32_t lo = f2tf32(av[u] - __uint_as_float(hi));
                ((uint32_t*)&AsL[sbase + (arow << 3) + ph])[c] = lo;
            }
        }
        {
            int k = bkrow;
            int p = ((k >> 3) << 2) | (k & 3);
            int c = (k >> 2) & 1;
#pragma unroll
            for (int u = 0; u < 8; u++) {
                int col = bcol + u;
                int ph = p ^ ((col & 3) << 1);
                uint32_t hi = f2tf32(bb[u]);
                ((uint32_t*)&BsH[sbase + (col << 3) + ph])[c] = hi;
                if (TERMS == 3) {
                    uint32_t lo = f2tf32(bb[u] - __uint_as_float(hi));
                    ((uint32_t*)&BsL[sbase + (col << 3) + ph])[c] = lo;
                }
            }
        }
    };

    auto compute = [&](int st) {
        const int sbase = st << 10;
#pragma unroll
        for (int hb = 0; hb < 2; hb++) {
            const int ph = (hb * 4 + tg) ^ ((g & 3) << 1);
            uint32_t afH[4][4];
            uint2 bH[4];
#pragma unroll
            for (int mt = 0; mt < 4; mt++) {
                int r = wr + mt * 16 + g;
                uint2 p0 = AsH[sbase + (r << 3) + ph];
                uint2 p1 = AsH[sbase + ((r + 8) << 3) + ph];
                afH[mt][0] = p0.x; afH[mt][1] = p1.x;
                afH[mt][2] = p0.y; afH[mt][3] = p1.y;
            }
#pragma unroll
            for (int ni = 0; ni < 4; ni++) {
                int cc = wc + ni * 8 + g;
                bH[ni] = BsH[sbase + (cc << 3) + ph];
            }
#pragma unroll
            for (int ni = 0; ni < 4; ni++)
#pragma unroll
                for (int mt = 0; mt < 4; mt++)
                    mma_tf32(acc[mt][ni], afH[mt], bH[ni].x, bH[ni].y);
            if (TERMS == 3) {
                uint2 bL[4];
#pragma unroll
                for (int ni = 0; ni < 4; ni++) {
                    int cc = wc + ni * 8 + g;
                    bL[ni] = BsL[sbase + (cc << 3) + ph];
                }
#pragma unroll
                for (int ni = 0; ni < 4; ni++)
#pragma unroll
                    for (int mt = 0; mt < 4; mt++)
                        mma_tf32(acc[mt][ni], afH[mt], bL[ni].x, bL[ni].y);
#pragma unroll
                for (int mt = 0; mt < 4; mt++) {
                    int r = wr + mt * 16 + g;
                    uint2 p0 = AsL[sbase + (r << 3) + ph];
                    uint2 p1 = AsL[sbase + ((r + 8) << 3) + ph];
                    uint32_t afL[4] = {p0.x, p1.x, p0.y, p1.y};
#pragma unroll
                    for (int ni = 0; ni < 4; ni++)
                        mma_tf32(acc[mt][ni], afL, bH[ni].x, bH[ni].y);
                }
            }
        }
    };

    loadG(kbeg);
    storeS(0);
    __syncthreads();

    const int nIter = Kc >> 4;
    for (int it = 0; it < nIter; it++) {
        int st = it & 1;
        bool hasNext = (it + 1 < nIter);
        if (hasNext) loadG(kbeg + (it + 1) * 16);
        compute(st);
        if (hasNext) storeS(st ^ 1);
        __syncthreads();
    }

    float* Cout = (S == 1) ? C : (Cpart + (size_t)blockIdx.z * N_TOK * M);
#pragma unroll
    for (int mt = 0; mt < 4; mt++) {
#pragma unroll
        for (int ni = 0; ni < 4; ni++) {
            int r = row0 + wr + mt * 16 + g;
            int c = col0 + wc + ni * 8 + tg * 2;
            if (c + 2 <= M) {
                *(float2*)&Cout[(size_t)r * M + c] =
                    make_float2(acc[mt][ni][0], acc[mt][ni][1]);
                *(float2*)&Cout[(size_t)(r + 8) * M + c] =
                    make_float2(acc[mt][ni][2], acc[mt][ni][3]);
            }
        }
    }
}

__global__ void splitk_reduce_kernel(const float* __restrict__ part,
                                     float* __restrict__ out, int len, int S)
{
    int i = blockIdx.x * 256 + threadIdx.x;
    if (i >= len) return;
    float s = 0.f;
    for (int z = 0; z < S; z++) s += part[(size_t)z * len + i];
    out[i] = s;
}

// ---------------- compressed k/v (pre-RoPE) --------------------------------
__global__ void compress_kernel(const float* __restrict__ k,
                                const float* __restrict__ v,
                                const float* __restrict__ pe,
                                float* __restrict__ ck,
                                float* __restrict__ cv)
{
    int m = blockIdx.x;
    int d = threadIdx.x;
    float sk = 0.f, sv = 0.f;
#pragma unroll 8
    for (int i = 0; i < KS; i++) {
        sk += k[(m*KS + i)*D + d] + pe[i*D + d];
        sv += v[(m*KS + i)*D + d];
    }
    ck[m*D + d] = sk * (1.f/KS);
    cv[m*D + d] = sv * (1.f/KS);
}

// ---------------- RoPE (in place) ------------------------------------------
__global__ void rope_kernel(float* __restrict__ x, int heads, int pos_stride)
{
    int row = blockIdx.x;
    int d   = threadIdx.x;    // 0..63
    float inv = powf(10000.f, -(float)d / 64.f);
    float ang = (float)(row * pos_stride) * inv;
    float c = cosf(ang), s = sinf(ang);
    for (int h = 0; h < heads; h++) {
        float* p = x + ((size_t)row*heads + h) * D;
        float x1 = p[d], x2 = p[d + 64];
        p[d]      = x1 * c - x2 * s;
        p[d + 64] = x2 * c + x1 * s;
    }
}

// ---------------- compressed attention: one block per token -----------------
__global__ void cmp_attn_kernel(const float* __restrict__ q,
                                const float* __restrict__ ck,
                                const float* __restrict__ cv,
                                float* __restrict__ out,
                                float* __restrict__ blks)
{
    int n = blockIdx.x;
    __shared__ float qs[HQ*D];
    __shared__ float pcs[HQ][NC];
    int tid = threadIdx.x;            // 256

    for (int e = tid; e < HQ*D/4; e += 256)
        ((float4*)qs)[e] = ((const float4*)(q + (size_t)n*HQ*D))[e];
    __syncthreads();

    for (int e = tid; e < HQ*NC; e += 256) {
        int h = e >> 6, m = e & (NC-1);
        float s = 0.f;
        const float* qp = qs + h*D;
        const float* cp = ck + m*D;
#pragma unroll 8
        for (int d = 0; d < D; d++) s += qp[d] * cp[d];
        s *= SCALE;
        bool valid = (n >= m*STRIDE + KS - 1);
        pcs[h][m] = valid ? s : NEGF;
    }
    __syncthreads();

    // warp-parallel softmax: warp w handles heads w and w+8
    {
        int w = tid >> 5, l = tid & 31;
        for (int h = w; h < HQ; h += 8) {
            float a = pcs[h][l], b = pcs[h][l + 32];
            float mx = fmaxf(a, b);
#pragma unroll
            for (int o = 16; o > 0; o >>= 1) mx = fmaxf(mx, __shfl_xor_sync(0xffffffff, mx, o));
            float ea = __expf(a - mx), eb = __expf(b - mx);
            float s = ea + eb;
#pragma unroll
            for (int o = 16; o > 0; o >>= 1) s += __shfl_xor_sync(0xffffffff, s, o);
            float inv = 1.f / s;
            bool va = (n >= l*STRIDE + KS - 1);
            bool vb = (n >= (l+32)*STRIDE + KS - 1);
            pcs[h][l]      = va ? ea * inv : 0.f;
            pcs[h][l + 32] = vb ? eb * inv : 0.f;
        }
    }
    __syncthreads();

    for (int m = tid; m < NC; m += 256) {
        float s = 0.f;
        for (int h = 0; h < HQ; h++) s += pcs[h][m];
        blks[(size_t)n*NC + m] = s;
    }

    for (int e = tid; e < HQ*D; e += 256) {
        int h = e >> 7, d = e & (D-1);
        float a = 0.f;
#pragma unroll 4
        for (int m = 0; m < NC; m++) a += pcs[h][m] * cv[m*D + d];
        out[(size_t)n*HQ*D + e] = a;
    }
}

// ---------------- top-k selection ------------------------------------------
__global__ void topk_kernel(const float* __restrict__ blks, int* __restrict__ topk)
{
    int n = blockIdx.x * blockDim.x + threadIdx.x;
    if (n >= N_TOK) return;
    float sel[NC];
    int tb = n / BSZ;
    for (int m = 0; m < NC; m++) {
        float s = blks[(size_t)n*NC + m];
        if (m > tb) s = NEGF;
        if (m < 1 || (m <= tb && m > tb - 2)) s = 1e30f;
        sel[m] = s;
    }
    for (int j = 0; j < TOPK; j++) {
        int bi = 0; float bv = sel[0];
        for (int m = 1; m < NC; m++) if (sel[m] > bv) { bv = sel[m]; bi = m; }
        topk[n*TOPK + j] = bi;
        sel[bi] = -FLT_MAX;
    }
}

// ============ SIMT helpers (sel attention) ==================================
#define KVP 132

__device__ __forceinline__ void attn_softmax_update(
    float* sc, float* mS, float* lS, float* fS, int tid)
{
    int h = tid >> 4, t = tid & 15;
    float4 sv = *(float4*)&sc[h*64 + t*4];
    float pm = fmaxf(fmaxf(sv.x, sv.y), fmaxf(sv.z, sv.w));
#pragma unroll
    for (int o = 1; o < 16; o <<= 1) pm = fmaxf(pm, __shfl_xor_sync(0xffffffff, pm, o));
    float mOld = mS[h];
    float mNew = fmaxf(mOld, pm);
    float4 p;
    p.x = __expf(sv.x - mNew); p.y = __expf(sv.y - mNew);
    p.z = __expf(sv.z - mNew); p.w = __expf(sv.w - mNew);
    *(float4*)&sc[h*64 + t*4] = p;
    float ps = p.x + p.y + p.z + p.w;
#pragma unroll
    for (int o = 1; o < 16; o <<= 1) ps += __shfl_xor_sync(0xffffffff, ps, o);
    if (t == 0) {
        float f = __expf(mOld - mNew);
        fS[h] = f;
        lS[h] = lS[h] * f + ps;
        mS[h] = mNew;
    }
}

__device__ __forceinline__ void attn_pv(
    const float* kv, const float* sc, float* acc, float f, int h, int d0, int tl)
{
#pragma unroll
    for (int i = 0; i < 8; i++) acc[i] *= f;
    for (int j = 0; j < tl; j++) {
        float p = sc[h*64 + j];
        float4 v0 = *(const float4*)&kv[j*KVP + d0];
        float4 v1 = *(const float4*)&kv[j*KVP + d0 + 4];
        acc[0] += p*v0.x; acc[1] += p*v0.y; acc[2] += p*v0.z; acc[3] += p*v0.w;
        acc[4] += p*v1.x; acc[5] += p*v1.y; acc[6] += p*v1.z; acc[7] += p*v1.w;
    }
}

// ---------------- selected (top-k) attention (SIMT, as round 5) -------------
__global__ void __launch_bounds__(256, 2)
sel_attn_kernel(const float* __restrict__ q, const float* __restrict__ k,
                const float* __restrict__ v, const int* __restrict__ topk,
                float* __restrict__ out)
{
    int n = blockIdx.x;
    int tid = threadIdx.x;
    __shared__ float qs[HQ*D];
    __shared__ float kv[64*KVP];
    __shared__ float sc[HQ*64];
    __shared__ int   posA[TOPK*BSZ];
    __shared__ float mS[HQ], lS[HQ], fS[HQ];

    for (int e = tid; e < HQ*D/4; e += 256)
        ((float4*)qs)[e] = ((const float4*)(q + (size_t)n*HQ*D))[e];
    if (tid < HQ) { mS[tid] = -FLT_MAX; lS[tid] = 0.f; }
    posA[tid] = topk[n*TOPK + (tid >> 5)] * BSZ + (tid & 31);

    int h  = tid >> 4;
    int d0 = (tid & 15) * 8;
    float acc[8];
#pragma unroll
    for (int i = 0; i < 8; i++) acc[i] = 0.f;
    __syncthreads();

    for (int t0 = 0; t0 < TOPK*BSZ; t0 += 64) {
        for (int e = tid; e < 64*32; e += 256) {
            int row = e >> 5, c = e & 31;
            *(float4*)&kv[row*KVP + c*4] = ((const float4*)(k + (size_t)posA[t0 + row]*D))[c];
        }
        __syncthreads();
        {
            int jj = tid & 63;
            int hb = (tid >> 6) * 4;
            bool valid = posA[t0 + jj] <= n;
            float s0=0.f,s1=0.f,s2=0.f,s3=0.f;
            if (valid) {
                const float4* kr = (const float4*)(kv + jj*KVP);
                const float4* q0 = (const float4*)(qs + (hb+0)*D);
                const float4* q1 = (const float4*)(qs + (hb+1)*D);
                const float4* q2 = (const float4*)(qs + (hb+2)*D);
                const float4* q3 = (const float4*)(qs + (hb+3)*D);
#pragma unroll
                for (int c = 0; c < 32; c++) {
                    float4 kk = kr[c];
                    float4 a;
                    a = q0[c]; s0 += a.x*kk.x + a.y*kk.y + a.z*kk.z + a.w*kk.w;
                    a = q1[c]; s1 += a.x*kk.x + a.y*kk.y + a.z*kk.z + a.w*kk.w;
                    a = q2[c]; s2 += a.x*kk.x + a.y*kk.y + a.z*kk.z + a.w*kk.w;
                    a = q3[c]; s3 += a.x*kk.x + a.y*kk.y + a.z*kk.z + a.w*kk.w;
                }
                sc[(hb+0)*64+jj]=s0*SCALE; sc[(hb+1)*64+jj]=s1*SCALE;
                sc[(hb+2)*64+jj]=s2*SCALE; sc[(hb+3)*64+jj]=s3*SCALE;
            } else {
                sc[(hb+0)*64+jj]=NEGF; sc[(hb+1)*64+jj]=NEGF;
                sc[(hb+2)*64+jj]=NEGF; sc[(hb+3)*64+jj]=NEGF;
            }
        }
        __syncthreads();
        attn_softmax_update(sc, mS, lS, fS, tid);
        __syncthreads();
        for (int e = tid; e < 64*32; e += 256) {
            int row = e >> 5, c = e & 31;
            *(float4*)&kv[row*KVP + c*4] = ((const float4*)(v + (size_t)posA[t0 + row]*D))[c];
        }
        __syncthreads();
        attn_pv(kv, sc, acc, fS[h], h, d0, 64);
        __syncthreads();
    }
    float inv = 1.f / lS[h];
    float4 o0 = make_float4(acc[0]*inv, acc[1]*inv, acc[2]*inv, acc[3]*inv);
    float4 o1 = make_float4(acc[4]*inv, acc[5]*inv, acc[6]*inv, acc[7]*inv);
    *(float4*)&out[((size_t)n*HQ + h)*D + d0]     = o0;
    *(float4*)&out[((size_t)n*HQ + h)*D + d0 + 4] = o1;
}

// ================= window attention via 3xTF32 tensor cores =================
// Block = (q-tile of 64 tokens, head). 256 threads / 8 warps.
// smem (uint2 units): Qh[8][64][8]=4096, Ql=4096, Bh[4096], Bl[4096] (K then V),
// Ph[4][64][8]=2048, Pl=2048; then float stats.
__global__ void __launch_bounds__(256, 1)
win_mma_kernel(const float* __restrict__ q, const float* __restrict__ k,
               const float* __restrict__ v, float* __restrict__ out)
{
    extern __shared__ uint2 smw[];
    uint2* Qh = smw;
    uint2* Ql = smw + 4096;
    uint2* Bh = smw + 8192;
    uint2* Bl = smw + 12288;
    uint2* Ph = smw + 16384;
    uint2* Pl = smw + 18432;
    float* stats = (float*)(smw + 20480);
    float* mS   = stats;        // [64]
    float* lS   = stats + 64;   // [64]
    float* fS   = stats + 128;  // [64]
    float* pmax = stats + 192;  // [64][2]
    float* psum = stats + 320;  // [64][2]

    const int tid = threadIdx.x;
    const int wid = tid >> 5, lane = tid & 31;
    const int g = lane >> 2, tg = lane & 3;
    const int qtile0 = blockIdx.x * 64;
    const int h = blockIdx.y;

    // load Q tile (64 rows x 128 d) -> hi/lo pair layout
    for (int e = tid; e < 64*32; e += 256) {
        int row = e >> 5, c4 = e & 31;
        float4 vq = *(const float4*)&q[(((size_t)(qtile0 + row))*HQ + h)*D + c4*4];
        float qv[4] = {vq.x, vq.y, vq.z, vq.w};
#pragma unroll
        for (int u = 0; u < 4; u++) {
            int d = c4*4 + u;
            int ch = d >> 4, kk = d & 15;
            int p = ((kk >> 3) << 2) | (kk & 3);
            int cc = (kk >> 2) & 1;
            int ph = p ^ ((row & 3) << 1);
            int idx = ch*512 + (row << 3) + ph;
            uint32_t hi = f2tf32(qv[u]);
            ((uint32_t*)&Qh[idx])[cc] = hi;
            ((uint32_t*)&Ql[idx])[cc] = f2tf32(qv[u] - __uint_as_float(hi));
        }
    }
    if (tid < 64) { mS[tid] = -3.0e38f; lS[tid] = 0.f; }

    // warp roles
    const int mtS = wid & 3, cg = wid >> 2;      // scores: rows mtS*16, cols cg*32
    const int mtP = wid & 3, dh = wid >> 2;      // PV: rows mtP*16, d-cols dh*64

    float oacc[8][4];                            // PV acc: 8 n-tiles x 4
#pragma unroll
    for (int ni = 0; ni < 8; ni++)
#pragma unroll
        for (int r = 0; r < 4; r++) oacc[ni][r] = 0.f;

    int klo = qtile0 - WIN; if (klo < 0) klo = 0;
    __syncthreads();

    for (int kt = klo; kt < qtile0 + 64; kt += 64) {
        // ---- load K tile: B operand [col=key][k=d], hi/lo
        for (int e = tid; e < 64*32; e += 256) {
            int key = e >> 5, c4 = e & 31;
            float4 vk = *(const float4*)&k[((size_t)(kt + key))*D + c4*4];
            float kv4[4] = {vk.x, vk.y, vk.z, vk.w};
#pragma unroll
            for (int u = 0; u < 4; u++) {
                int d = c4*4 + u;
                int ch = d >> 4, kk = d & 15;
                int p = ((kk >> 3) << 2) | (kk & 3);
                int cc = (kk >> 2) & 1;
                int ph = p ^ ((key & 3) << 1);
                int idx = ch*512 + (key << 3) + ph;
                uint32_t hi = f2tf32(kv4[u]);
                ((uint32_t*)&Bh[idx])[cc] = hi;
                ((uint32_t*)&Bl[idx])[cc] = f2tf32(kv4[u] - __uint_as_float(hi));
            }
        }
        __syncthreads();   // K ready (and prev PV done via loop-end sync)

        // ---- scores S = Q @ K^T (3-term), warp tile 16x32
        float sacc[4][4];
#pragma unroll
        for (int ni = 0; ni < 4; ni++)
#pragma unroll
            for (int r = 0; r < 4; r++) sacc[ni][r] = 0.f;

#pragma unroll
        for (int ch = 0; ch < 8; ch++) {
#pragma unroll
            for (int hb = 0; hb < 2; hb++) {
                const int ph = (hb*4 + tg) ^ ((g & 3) << 1);
                int r = mtS*16 + g;
                uint2 a0 = Qh[ch*512 + (r << 3) + ph];
                uint2 a1 = Qh[ch*512 + ((r + 8) << 3) + ph];
                uint32_t afH[4] = {a0.x, a1.x, a0.y, a1.y};
                uint2 l0 = Ql[ch*512 + (r << 3) + ph];
                uint2 l1 = Ql[ch*512 + ((r + 8) << 3) + ph];
                uint32_t afL[4] = {l0.x, l1.x, l0.y, l1.y};
#pragma unroll
                for (int ni = 0; ni < 4; ni++) {
                    int col = cg*32 + ni*8 + g;
                    uint2 bH = Bh[ch*512 + (col << 3) + ph];
                    uint2 bL = Bl[ch*512 + (col << 3) + ph];
                    mma_tf32(sacc[ni], afH, bH.x, bH.y);
                    mma_tf32(sacc[ni], afH, bL.x, bL.y);
                    mma_tf32(sacc[ni], afL, bH.x, bH.y);
                }
            }
        }

        // ---- scale + mask + warp-partial row max
        const int rA = qtile0 + mtS*16 + g;      // global q pos row A
        const int rB = rA + 8;
        float m1 = -3.0e38f, m2 = -3.0e38f;
#pragma unroll
        for (int ni = 0; ni < 4; ni++) {
            int key0 = kt + cg*32 + ni*8 + tg*2;
#pragma unroll
            for (int i = 0; i < 4; i++) {
                int key = key0 + (i & 1);
                int qp = (i < 2) ? rA : rB;
                float s = sacc[ni][i] * SCALE;
                bool valid = (key <= qp) && (key >= qp - WIN);
                s = valid ? s : NEGF;
                sacc[ni][i] = s;
                if (i < 2) m1 = fmaxf(m1, s); else m2 = fmaxf(m2, s);
            }
        }
#pragma unroll
        for (int o = 1; o < 4; o <<= 1) {
            m1 = fmaxf(m1, __shfl_xor_sync(0xffffffff, m1, o));
            m2 = fmaxf(m2, __shfl_xor_sync(0xffffffff, m2, o));
        }
        int rlA = mtS*16 + g, rlB = rlA + 8;
        if (tg == 0) { pmax[rlA*2 + cg] = m1; pmax[rlB*2 + cg] = m2; }
        __syncthreads();   // pmax ready; all scores mma done -> B buffer free

        // ---- p = exp(s - mNew), store P hi/lo, partial sums; V load
        float mnA = fmaxf(mS[rlA], fmaxf(pmax[rlA*2], pmax[rlA*2+1]));
        float mnB = fmaxf(mS[rlB], fmaxf(pmax[rlB*2], pmax[rlB*2+1]));
        float sumA = 0.f, sumB = 0.f;
#pragma unroll
        for (int ni = 0; ni < 4; ni++) {
#pragma unroll
            for (int i = 0; i < 4; i++) {
                float s = sacc[ni][i];
                float mn = (i < 2) ? mnA : mnB;
                float p = (s <= -1e29f) ? 0.f : __expf(s - mn);
                if (i < 2) sumA += p; else sumB += p;
                // store to P (A-operand pair layout), k-dim = key (64 -> 4 chunks)
                int cloc = cg*32 + ni*8 + tg*2 + (i & 1);
                int ch = cloc >> 4, kk = cloc & 15;
                int pp = ((kk >> 3) << 2) | (kk & 3);
                int cc = (kk >> 2) & 1;
                int rl = (i < 2) ? rlA : rlB;
                int ph = pp ^ ((rl & 3) << 1);
                int idx = ch*512 + (rl << 3) + ph;
                uint32_t hi = f2tf32(p);
                ((uint32_t*)&Ph[idx])[cc] = hi;
                ((uint32_t*)&Pl[idx])[cc] = f2tf32(p - __uint_as_float(hi));
            }
        }
#pragma unroll
        for (int o = 1; o < 4; o <<= 1) {
            sumA += __shfl_xor_sync(0xffffffff, sumA, o);
            sumB += __shfl_xor_sync(0xffffffff, sumB, o);
        }
        if (tg == 0) { psum[rlA*2 + cg] = sumA; psum[rlB*2 + cg] = sumB; }

        // V tile -> B operand [col=d (128)][k=key], chunk stride 1024
        for (int e = tid; e < 64*32; e += 256) {
            int key = e >> 5, c4 = e & 31;
            float4 vv = *(const float4*)&v[((size_t)(kt + key))*D + c4*4];
            float v4[4] = {vv.x, vv.y, vv.z, vv.w};
            int chv = key >> 4, kkv = key & 15;
            int pv = ((kkv >> 3) << 2) | (kkv & 3);
            int ccv = (kkv >> 2) & 1;
#pragma unroll
            for (int u = 0; u < 4; u++) {
                int d = c4*4 + u;
                int phv = pv ^ ((d & 3) << 1);
                int idx = chv*1024 + (d << 3) + phv;
                uint32_t hi = f2tf32(v4[u]);
                ((uint32_t*)&Bh[idx])[ccv] = hi;
                ((uint32_t*)&Bl[idx])[ccv] = f2tf32(v4[u] - __uint_as_float(hi));
            }
        }
        __syncthreads();   // psum + P + V ready

        // ---- update running stats (one thread per row)
        if (tid < 64) {
            float mo = mS[tid];
            float mn = fmaxf(mo, fmaxf(pmax[tid*2], pmax[tid*2+1]));
            float f = __expf(mo - mn);
            lS[tid] = lS[tid] * f + psum[tid*2] + psum[tid*2+1];
            mS[tid] = mn;
            fS[tid] = f;
        }
        __syncthreads();   // fS/lS/mS ready

        // ---- PV: out += P @ V (3-term), warp tile 16 rows x 64 d-cols
        {
            int rl1 = mtP*16 + g, rl2 = rl1 + 8;
            float f1 = fS[rl1], f2 = fS[rl2];
#pragma unroll
            for (int ni = 0; ni < 8; ni++) {
                oacc[ni][0] *= f1; oacc[ni][1] *= f1;
                oacc[ni][2] *= f2; oacc[ni][3] *= f2;
            }
#pragma unroll
            for (int ch = 0; ch < 4; ch++) {
#pragma unroll
                for (int hb = 0; hb < 2; hb++) {
                    const int ph = (hb*4 + tg) ^ ((g & 3) << 1);
                    int r = mtP*16 + g;
                    uint2 a0 = Ph[ch*512 + (r << 3) + ph];
                    uint2 a1 = Ph[ch*512 + ((r + 8) << 3) + ph];
                    uint32_t afH[4] = {a0.x, a1.x, a0.y, a1.y};
                    uint2 l0 = Pl[ch*512 + (r << 3) + ph];
                    uint2 l1 = Pl[ch*512 + ((r + 8) << 3) + ph];
                    uint32_t afL[4] = {l0.x, l1.x, l0.y, l1.y};
#pragma unroll
                    for (int ni = 0; ni < 8; ni++) {
                        int col = dh*64 + ni*8 + g;
                        uint2 bH = Bh[ch*1024 + (col << 3) + ph];
                        uint2 bL = Bl[ch*1024 + (col << 3) + ph];
                        mma_tf32(oacc[ni], afH, bH.x, bH.y);
                        mma_tf32(oacc[ni], afH, bL.x, bL.y);
                        mma_tf32(oacc[ni], afL, bH.x, bH.y);
                    }
                }
            }
        }
        __syncthreads();   // PV done -> B buffer free for next K tile
    }

    // epilogue: divide by lS, write out[n][h][d]
    {
        int rl1 = mtP*16 + g, rl2 = rl1 + 8;
        float i1 = 1.f / lS[rl1], i2 = 1.f / lS[rl2];
        size_t b1 = ((size_t)(qtile0 + rl1)*HQ + h)*D;
        size_t b2 = ((size_t)(qtile0 + rl2)*HQ + h)*D;
#pragma unroll
        for (int ni = 0; ni < 8; ni++) {
            int d = dh*64 + ni*8 + tg*2;
            *(float2*)&out[b1 + d] = make_float2(oacc[ni][0]*i1, oacc[ni][1]*i1);
            *(float2*)&out[b2 + d] = make_float2(oacc[ni][2]*i2, oacc[ni][3]*i2);
        }
    }
}

// ---------------- gate combine ---------------------------------------------
__global__ void combine_kernel(const float* __restrict__ gbuf,
                               const float* __restrict__ cmp,
                               const float* __restrict__ sp,
                               const float* __restrict__ sw,
                               float* __restrict__ att)
{
    size_t idx = (size_t)blockIdx.x * 256 + threadIdx.x;
    int n = (int)(idx >> 11);
    int hd = (int)(idx & 2047);
    int h = hd >> 7;
    const float* g = gbuf + (size_t)n*HQ*3 + h*3;
    float g0 = 1.f / (1.f + __expf(-g[0]));
    float g1 = 1.f / (1.f + __expf(-g[1]));
    float g2 = 1.f / (1.f + __expf(-g[2]));
    att[idx] = g0 * cmp[idx] + g1 * sp[idx] + g2 * sw[idx];
}

// ---------------- launcher --------------------------------------------------
extern "C" void kernel_launch(void* const* d_in, const int* in_sizes, int n_in,
                              void* d_out, int out_size)
{
    const float* x  = (const float*)d_in[0];
    const float* Wq = (const float*)d_in[2];
    const float* Wk = (const float*)d_in[3];
    const float* Wv = (const float*)d_in[4];
    const float* Wo = (const float*)d_in[5];
    const float* Wg = (const float*)d_in[6];
    const float* pe = (const float*)d_in[7];
    float* out = (float*)d_out;

    float *q, *k, *v, *ck, *cv, *blks, *cmp, *sp, *sw, *gate, *att, *part;
    int* tk;
    cudaGetSymbolAddress((void**)&q,    g_q);
    cudaGetSymbolAddress((void**)&k,    g_k);
    cudaGetSymbolAddress((void**)&v,    g_v);
    cudaGetSymbolAddress((void**)&ck,   g_ck);
    cudaGetSymbolAddress((void**)&cv,   g_cv);
    cudaGetSymbolAddress((void**)&blks, g_blks);
    cudaGetSymbolAddress((void**)&tk,   g_topk);
    cudaGetSymbolAddress((void**)&cmp,  g_cmp);
    cudaGetSymbolAddress((void**)&sp,   g_sp);
    cudaGetSymbolAddress((void**)&sw,   g_sw);
    cudaGetSymbolAddress((void**)&gate, g_gate);
    cudaGetSymbolAddress((void**)&att,  g_att);
    cudaGetSymbolAddress((void**)&part, g_part);

    const int SMEM3 = 65536;
    const int SMEM1 = 32768;
    const int SMEMW = 20480*8 + 448*4;   // 165632 B
    cudaFuncSetAttribute(gemm_kernel<3>, cudaFuncAttributeMaxDynamicSharedMemorySize, SMEM3);
    cudaFuncSetAttribute(gemm_kernel<1>, cudaFuncAttributeMaxDynamicSharedMemorySize, SMEM1);
    cudaFuncSetAttribute(win_mma_kernel, cudaFuncAttributeMaxDynamicSharedMemorySize, SMEMW);

    // projections
    gemm_kernel<3><<<dim3(16, 16, 1), 256, SMEM3>>>(x, Wq, q, nullptr, HID, HQ*D);
    gemm_kernel<3><<<dim3(1, 16, 8), 256, SMEM3>>>(x, Wk, k, part, HID, D);
    splitk_reduce_kernel<<<(N_TOK*D + 255)/256, 256>>>(part, k, N_TOK*D, 8);
    gemm_kernel<3><<<dim3(1, 16, 8), 256, SMEM3>>>(x, Wv, v, part, HID, D);
    splitk_reduce_kernel<<<(N_TOK*D + 255)/256, 256>>>(part, v, N_TOK*D, 8);
    gemm_kernel<1><<<dim3(1, 16, 8), 256, SMEM1>>>(x, Wg, gate, part, HID, HQ*3);
    splitk_reduce_kernel<<<(N_TOK*HQ*3 + 255)/256, 256>>>(part, gate, N_TOK*HQ*3, 8);

    // compress (pre-RoPE k), then RoPE
    compress_kernel<<<NC, D>>>(k, v, pe, ck, cv);
    rope_kernel<<<N_TOK, 64>>>(q, HQ, 1);
    rope_kernel<<<N_TOK, 64>>>(k, 1, 1);
    rope_kernel<<<NC, 64>>>(ck, 1, STRIDE);

    // branches
    cmp_attn_kernel<<<N_TOK, 256>>>(q, ck, cv, cmp, blks);
    topk_kernel<<<N_TOK/256, 256>>>(blks, tk);
    sel_attn_kernel<<<N_TOK, 256>>>(q, k, v, tk, sp);
    win_mma_kernel<<<dim3(32, HQ), 256, SMEMW>>>(q, k, v, sw);

    // gate combine + output projection
    combine_kernel<<<(N_TOK*HQ*D)/256, 256>>>(gate, cmp, sp, sw, att);
    gemm_kernel<1><<<dim3(16, 16, 1), 256, SMEM1>>>(att, Wo, out, nullptr, HID, HID);
}